// round 6
// baseline (speedup 1.0000x reference)
#include <cuda_runtime.h>
#include <cuda_fp16.h>
#include <stdint.h>
#include <math.h>

// B=64, T=64, D=8, F=1024, H=1024, C=22, IN=4096, N=B*T=4096
#define NROWS 4096
#define FDIM  1024
#define HDIM  1024
#define INDIM 4096
#define DSTEPS 8
#define CDIM  22

// ---------------- scratch (device globals) ----------------------------------
__device__ float g_h[NROWS * HDIM];          // encoder h (fp32)
__device__ float g_c[NROWS * HDIM];          // decoder cell state
__device__ float g_bsum_dec[4 * HDIM];       // gate-interleaved bias
__device__ float g_bsum_enc[4 * FDIM];

__device__ __align__(256) __half g_x16[NROWS * INDIM];
__device__ __align__(256) __half g_Wfh[FDIM * INDIM],  g_Wfl[FDIM * INDIM];
__device__ __align__(256) __half g_dWihh[4 * HDIM * FDIM], g_dWihl[4 * HDIM * FDIM];
__device__ __align__(256) __half g_dWhhh[4 * HDIM * HDIM], g_dWhhl[4 * HDIM * HDIM];
__device__ __align__(256) __half g_Wdch[FDIM * HDIM],  g_Wdcl[FDIM * HDIM];
__device__ __align__(256) __half g_eWihh[4 * FDIM * FDIM], g_eWihl[4 * FDIM * FDIM];
__device__ __align__(256) __half g_eWhhh[4 * FDIM * FDIM], g_eWhhl[4 * FDIM * FDIM];
__device__ __align__(256) __half g_f16[NROWS * FDIM];
__device__ __align__(256) __half g_h16a[NROWS * HDIM];   // double-buffered hidden
__device__ __align__(256) __half g_h16b[NROWS * HDIM];
__device__ __align__(256) __half g_d16[NROWS * FDIM];

// ---------------- PTX helpers ------------------------------------------------
__device__ __forceinline__ uint32_t smem_u32(const void* p) {
    uint32_t a;
    asm("{ .reg .u64 t; cvta.to.shared.u64 t, %1; cvt.u32.u64 %0, t; }" : "=r"(a) : "l"(p));
    return a;
}
__device__ __forceinline__ void cpa16(uint32_t sa, const void* g) {
    asm volatile("cp.async.cg.shared.global [%0], [%1], 16;" :: "r"(sa), "l"(g));
}
__device__ __forceinline__ void cp_commit() {
    asm volatile("cp.async.commit_group;" ::: "memory");
}
template<int N> __device__ __forceinline__ void cp_wait() {
    asm volatile("cp.async.wait_group %0;" :: "n"(N) : "memory");
}
__device__ __forceinline__ void ldmx4(uint32_t* r, uint32_t addr) {
    asm volatile("ldmatrix.sync.aligned.m8n8.x4.shared.b16 {%0,%1,%2,%3}, [%4];"
                 : "=r"(r[0]), "=r"(r[1]), "=r"(r[2]), "=r"(r[3]) : "r"(addr));
}
__device__ __forceinline__ void mma16816(float* c, const uint32_t* a, const uint32_t* b) {
    asm volatile("mma.sync.aligned.m16n8k16.row.col.f32.f16.f16.f32 "
                 "{%0,%1,%2,%3}, {%4,%5,%6,%7}, {%8,%9}, {%0,%1,%2,%3};"
                 : "+f"(c[0]), "+f"(c[1]), "+f"(c[2]), "+f"(c[3])
                 : "r"(a[0]), "r"(a[1]), "r"(a[2]), "r"(a[3]), "r"(b[0]), "r"(b[1]));
}
__device__ __forceinline__ uint32_t swz(int row, int g) {
    return (uint32_t)(row * 128 + ((g ^ (row & 7)) << 4));
}
__device__ __forceinline__ float sigmoidf_(float x) { return 1.0f / (1.0f + expf(-x)); }

// ---------------- tensor GEMM ------------------------------------------------
// C[128,256] tile = A[128,K]fp16 @ (B_hi + B_lo)[256,K]^T over two K-sources.
// cell=0: plain epilogue (bias/relu/C/fp16-E).
// cell=1: decoder LSTM (gate-interleaved cols; writes c fp32 + h16o).
// cell=2: encoder LSTM (writes h fp32; c0=0).
#define T_A  0
#define T_BH 16384
#define T_BL 49152
#define STAGE_SZ 81920
#define TG_SMEM (2 * STAGE_SZ)

__global__ __launch_bounds__(256, 1)
void tgemm(const __half* __restrict__ A1, int lda1,
           const __half* __restrict__ B1h, const __half* __restrict__ B1l, int ldb1, int nk1,
           const __half* __restrict__ A2, int lda2,
           const __half* __restrict__ B2h, const __half* __restrict__ B2l, int ldb2, int nk2,
           const float* __restrict__ bias, float* __restrict__ C, int ldc,
           __half* __restrict__ E, int lde, float escale, int relu,
           int cell, const float* __restrict__ cin, float* __restrict__ cout,
           __half* __restrict__ h16o, float* __restrict__ hfo, int czero)
{
    extern __shared__ __align__(1024) char sm[];
    const int tid = threadIdx.x;
    const int wid = tid >> 5;
    const int lane = tid & 31;
    const int wm = wid >> 2;
    const int wn = wid & 3;
    const int bm = blockIdx.y * 128;
    const int bn = blockIdx.x * 256;
    const uint32_t smb = smem_u32(sm);
    const int total = nk1 + nk2;

    float acc[4][8][4];
#pragma unroll
    for (int i = 0; i < 4; i++)
#pragma unroll
        for (int j = 0; j < 8; j++)
#pragma unroll
            for (int k = 0; k < 4; k++) acc[i][j][k] = 0.0f;

    auto load_stage = [&](int q, int s) {
        const __half *a, *bh, *bl; int la, lb, k0;
        if (q < nk1) { a = A1; bh = B1h; bl = B1l; la = lda1; lb = ldb1; k0 = q * 64; }
        else         { a = A2; bh = B2h; bl = B2l; la = lda2; lb = ldb2; k0 = (q - nk1) * 64; }
        const uint32_t sb = smb + (uint32_t)s * STAGE_SZ;
#pragma unroll
        for (int i = 0; i < 4; i++) {
            int v = tid + i * 256;
            int row = v >> 3, g = v & 7;
            cpa16(sb + T_A + swz(row, g), a + (size_t)(bm + row) * la + k0 + g * 8);
        }
#pragma unroll
        for (int i = 0; i < 8; i++) {
            int v = tid + i * 256;
            int row = v >> 3, g = v & 7;
            uint32_t so = swz(row, g);
            cpa16(sb + T_BH + so, bh + (size_t)(bn + row) * lb + k0 + g * 8);
            cpa16(sb + T_BL + so, bl + (size_t)(bn + row) * lb + k0 + g * 8);
        }
        cp_commit();
    };

    const int r8 = lane & 7;
    const int arow0 = wm * 64 + r8 + 8 * ((lane >> 3) & 1);
    const int akq   = lane >> 4;
    const int brow0 = wn * 64 + r8 + 8 * (lane >> 4);
    const int bkq   = (lane >> 3) & 1;

    load_stage(0, 0);

    for (int q = 0; q < total; q++) {
        const int s = q & 1;
        if (q + 1 < total) { load_stage(q + 1, s ^ 1); cp_wait<1>(); }
        else               { cp_wait<0>(); }
        __syncthreads();

        const uint32_t sb = smb + (uint32_t)s * STAGE_SZ;
#pragma unroll
        for (int ks = 0; ks < 4; ks++) {
            uint32_t a[4][4];
#pragma unroll
            for (int mt = 0; mt < 4; mt++)
                ldmx4(a[mt], sb + T_A + swz(arow0 + mt * 16, ks * 2 + akq));
            {
                uint32_t b[8][2];
#pragma unroll
                for (int p = 0; p < 4; p++) {
                    uint32_t t[4];
                    ldmx4(t, sb + T_BH + swz(brow0 + p * 16, ks * 2 + bkq));
                    b[2 * p][0] = t[0]; b[2 * p][1] = t[1];
                    b[2 * p + 1][0] = t[2]; b[2 * p + 1][1] = t[3];
                }
#pragma unroll
                for (int mt = 0; mt < 4; mt++)
#pragma unroll
                    for (int nt = 0; nt < 8; nt++)
                        mma16816(acc[mt][nt], a[mt], b[nt]);
            }
            {
                uint32_t b[8][2];
#pragma unroll
                for (int p = 0; p < 4; p++) {
                    uint32_t t[4];
                    ldmx4(t, sb + T_BL + swz(brow0 + p * 16, ks * 2 + bkq));
                    b[2 * p][0] = t[0]; b[2 * p][1] = t[1];
                    b[2 * p + 1][0] = t[2]; b[2 * p + 1][1] = t[3];
                }
#pragma unroll
                for (int mt = 0; mt < 4; mt++)
#pragma unroll
                    for (int nt = 0; nt < 8; nt++)
                        mma16816(acc[mt][nt], a[mt], b[nt]);
            }
        }
        __syncthreads();
    }

    if (cell == 0) {
        // ---- plain epilogue ----
#pragma unroll
        for (int mt = 0; mt < 4; mt++) {
#pragma unroll
            for (int nt = 0; nt < 8; nt++) {
                const int row = bm + wm * 64 + mt * 16 + (lane >> 2);
                const int col = bn + wn * 64 + nt * 8 + (lane & 3) * 2;
#pragma unroll
                for (int hh2 = 0; hh2 < 2; hh2++) {
                    const int rr = row + hh2 * 8;
                    float v0 = acc[mt][nt][2 * hh2];
                    float v1 = acc[mt][nt][2 * hh2 + 1];
                    if (bias) { v0 += bias[col]; v1 += bias[col + 1]; }
                    if (relu) { v0 = fmaxf(v0, 0.0f); v1 = fmaxf(v1, 0.0f); }
                    if (C)
                        *reinterpret_cast<float2*>(C + (size_t)rr * ldc + col) = make_float2(v0, v1);
                    if (E) {
                        __half2 hp;
                        hp.x = __float2half_rn(v0 * escale);
                        hp.y = __float2half_rn(v1 * escale);
                        *reinterpret_cast<__half2*>(E + (size_t)rr * lde + col) = hp;
                    }
                }
            }
        }
    } else {
        // ---- fused LSTM-cell epilogue (gate-interleaved columns) ----
        const int Hd = HDIM;
#pragma unroll
        for (int mt = 0; mt < 4; mt++) {
#pragma unroll
            for (int nt = 0; nt < 8; nt++) {
                const int r0 = bm + wm * 64 + mt * 16 + (lane >> 2);
                const int gc = bn + wn * 64 + nt * 8 + (lane & 3) * 2;
                float v0 = acc[mt][nt][0] + bias[gc];
                float v1 = acc[mt][nt][1] + bias[gc + 1];
                float v2 = acc[mt][nt][2] + bias[gc];
                float v3 = acc[mt][nt][3] + bias[gc + 1];
                float o0 = __shfl_xor_sync(0xffffffffu, v0, 1);
                float o1 = __shfl_xor_sync(0xffffffffu, v1, 1);
                float o2 = __shfl_xor_sync(0xffffffffu, v2, 1);
                float o3 = __shfl_xor_sync(0xffffffffu, v3, 1);
                float iv, fv, gv, ov; int row;
                if ((lane & 1) == 0) { iv = v0; fv = v1; gv = o0; ov = o1; row = r0; }
                else                 { iv = o2; fv = o3; gv = v2; ov = v3; row = r0 + 8; }
                const int j = gc >> 2;
                const size_t oidx = (size_t)row * Hd + j;
                float cprev = czero ? 0.0f : cin[oidx];
                float cn = sigmoidf_(fv) * cprev + sigmoidf_(iv) * tanhf(gv);
                float hn = sigmoidf_(ov) * tanhf(cn);
                if (cout) cout[oidx] = cn;
                if (h16o) h16o[oidx] = __float2half_rn(hn);
                if (hfo)  hfo[oidx] = hn;
            }
        }
    }
}

// ---------------- SIMT GEMM for tiny N=22 ------------------------------------
__global__ __launch_bounds__(256, 2)
void gemm_tn(const float* __restrict__ A, int lda,
             const float* __restrict__ B, int ldb,
             const float* __restrict__ bias,
             float* __restrict__ C, int ldc,
             int M, int N, int K)
{
    __shared__ float As[16][132];
    __shared__ float Bs[16][132];
    const int tid = threadIdx.x;
    const int bm = blockIdx.y * 128;
    const int bn = blockIdx.x * 128;
    const int tm = (tid >> 4) << 3;
    const int tn = (tid & 15) << 3;
    const int lr = tid >> 2;
    const int lc = (tid & 3) << 2;

    float acc[8][8];
#pragma unroll
    for (int i = 0; i < 8; i++)
#pragma unroll
        for (int j = 0; j < 8; j++) acc[i][j] = 0.0f;

    for (int k0 = 0; k0 < K; k0 += 16) {
#pragma unroll
        for (int h2 = 0; h2 < 2; h2++) {
            int r = lr + h2 * 64;
            const float4 v = *reinterpret_cast<const float4*>(&A[(size_t)(bm + r) * lda + k0 + lc]);
            As[lc + 0][r] = v.x; As[lc + 1][r] = v.y;
            As[lc + 2][r] = v.z; As[lc + 3][r] = v.w;
        }
#pragma unroll
        for (int h2 = 0; h2 < 2; h2++) {
            int r = lr + h2 * 64;
            float4 v = make_float4(0.f, 0.f, 0.f, 0.f);
            if (bn + r < N)
                v = *reinterpret_cast<const float4*>(&B[(size_t)(bn + r) * ldb + k0 + lc]);
            Bs[lc + 0][r] = v.x; Bs[lc + 1][r] = v.y;
            Bs[lc + 2][r] = v.z; Bs[lc + 3][r] = v.w;
        }
        __syncthreads();
#pragma unroll
        for (int k = 0; k < 16; k++) {
            float a[8], b[8];
            *reinterpret_cast<float4*>(&a[0]) = *reinterpret_cast<const float4*>(&As[k][tm]);
            *reinterpret_cast<float4*>(&a[4]) = *reinterpret_cast<const float4*>(&As[k][tm + 4]);
            *reinterpret_cast<float4*>(&b[0]) = *reinterpret_cast<const float4*>(&Bs[k][tn]);
            *reinterpret_cast<float4*>(&b[4]) = *reinterpret_cast<const float4*>(&Bs[k][tn + 4]);
#pragma unroll
            for (int i = 0; i < 8; i++)
#pragma unroll
                for (int j = 0; j < 8; j++)
                    acc[i][j] += a[i] * b[j];
        }
        __syncthreads();
    }
#pragma unroll
    for (int i = 0; i < 8; i++) {
        const int row = bm + tm + i;
        float* crow = C + (size_t)row * ldc;
#pragma unroll
        for (int j = 0; j < 8; j++) {
            const int col = bn + tn + j;
            if (col < N) {
                float v = acc[i][j];
                if (bias) v += bias[col];
                crow[col] = v;
            }
        }
    }
}

// ---------------- conversion kernels -----------------------------------------
__global__ void bias_perm(const float* __restrict__ a, const float* __restrict__ b,
                          float* __restrict__ out, int H)
{
    int i = blockIdx.x * blockDim.x + threadIdx.x;
    if (i >= 4 * H) return;
    int gate = i / H, unit = i - gate * H;
    out[unit * 4 + gate] = a[i] + b[i];
}

__global__ void cvt_wpair(const float* __restrict__ src,
                          __half* __restrict__ hi, __half* __restrict__ lo, int n)
{
    int i = (blockIdx.x * blockDim.x + threadIdx.x) * 4;
    if (i >= n) return;
    float4 v = *reinterpret_cast<const float4*>(src + i);
    float f[4] = { v.x, v.y, v.z, v.w };
    __half h[4], l[4];
#pragma unroll
    for (int k = 0; k < 4; k++) {
        h[k] = __float2half_rn(f[k]);
        l[k] = __float2half_rn(f[k] - __half2float(h[k]));
    }
    __half2 hp0; hp0.x = h[0]; hp0.y = h[1];
    __half2 hp1; hp1.x = h[2]; hp1.y = h[3];
    __half2 lp0; lp0.x = l[0]; lp0.y = l[1];
    __half2 lp1; lp1.x = l[2]; lp1.y = l[3];
    *reinterpret_cast<__half2*>(hi + i) = hp0;
    *reinterpret_cast<__half2*>(hi + i + 2) = hp1;
    *reinterpret_cast<__half2*>(lo + i) = lp0;
    *reinterpret_cast<__half2*>(lo + i + 2) = lp1;
}

__global__ void cvt_wpair_perm(const float* __restrict__ src,
                               __half* __restrict__ hi, __half* __restrict__ lo,
                               int H, int K, int n)
{
    int i = (blockIdx.x * blockDim.x + threadIdx.x) * 4;
    if (i >= n) return;
    int r = i / K, k = i - r * K;
    int gate = r / H, unit = r - gate * H;
    int o = (unit * 4 + gate) * K + k;
    float4 v = *reinterpret_cast<const float4*>(src + i);
    float f[4] = { v.x, v.y, v.z, v.w };
    __half h[4], l[4];
#pragma unroll
    for (int kk = 0; kk < 4; kk++) {
        h[kk] = __float2half_rn(f[kk]);
        l[kk] = __float2half_rn(f[kk] - __half2float(h[kk]));
    }
    __half2 hp0; hp0.x = h[0]; hp0.y = h[1];
    __half2 hp1; hp1.x = h[2]; hp1.y = h[3];
    __half2 lp0; lp0.x = l[0]; lp0.y = l[1];
    __half2 lp1; lp1.x = l[2]; lp1.y = l[3];
    *reinterpret_cast<__half2*>(hi + o) = hp0;
    *reinterpret_cast<__half2*>(hi + o + 2) = hp1;
    *reinterpret_cast<__half2*>(lo + o) = lp0;
    *reinterpret_cast<__half2*>(lo + o + 2) = lp1;
}

__global__ void cvt_h(const float* __restrict__ src, __half* __restrict__ dst, int n)
{
    int i = (blockIdx.x * blockDim.x + threadIdx.x) * 8;
    if (i >= n) return;
    float4 v0 = *reinterpret_cast<const float4*>(src + i);
    float4 v1 = *reinterpret_cast<const float4*>(src + i + 4);
    __half2 p0; p0.x = __float2half_rn(v0.x); p0.y = __float2half_rn(v0.y);
    __half2 p1; p1.x = __float2half_rn(v0.z); p1.y = __float2half_rn(v0.w);
    __half2 p2; p2.x = __float2half_rn(v1.x); p2.y = __float2half_rn(v1.y);
    __half2 p3; p3.x = __float2half_rn(v1.z); p3.y = __float2half_rn(v1.w);
    *reinterpret_cast<__half2*>(dst + i) = p0;
    *reinterpret_cast<__half2*>(dst + i + 2) = p1;
    *reinterpret_cast<__half2*>(dst + i + 4) = p2;
    *reinterpret_cast<__half2*>(dst + i + 6) = p3;
}

// ---------------- launch -----------------------------------------------------
extern "C" void kernel_launch(void* const* d_in, const int* in_sizes, int n_in,
                              void* d_out, int out_size)
{
    const float* x    = (const float*)d_in[0];
    const float* Wf   = (const float*)d_in[1];
    const float* bf_  = (const float*)d_in[2];
    const float* dWih = (const float*)d_in[3];
    const float* dWhh = (const float*)d_in[4];
    const float* dbih = (const float*)d_in[5];
    const float* dbhh = (const float*)d_in[6];
    const float* Wdc  = (const float*)d_in[7];
    const float* bdc  = (const float*)d_in[8];
    const float* eWih = (const float*)d_in[9];
    const float* eWhh = (const float*)d_in[10];
    const float* ebih = (const float*)d_in[11];
    const float* ebhh = (const float*)d_in[12];
    const float* Wec  = (const float*)d_in[13];
    const float* bec  = (const float*)d_in[14];

    float* out = (float*)d_out;
    float* dec = out + 64 * 64 * CDIM;

    float *h, *c, *bsd, *bse;
    __half *x16, *Wfh, *Wfl, *dWihh_, *dWihl_, *dWhhh_, *dWhhl_, *Wdch, *Wdcl;
    __half *eWihh_, *eWihl_, *eWhhh_, *eWhhl_, *f16, *h16a, *h16b, *d16;
    cudaGetSymbolAddress((void**)&h, g_h);
    cudaGetSymbolAddress((void**)&c, g_c);
    cudaGetSymbolAddress((void**)&bsd, g_bsum_dec);
    cudaGetSymbolAddress((void**)&bse, g_bsum_enc);
    cudaGetSymbolAddress((void**)&x16, g_x16);
    cudaGetSymbolAddress((void**)&Wfh, g_Wfh); cudaGetSymbolAddress((void**)&Wfl, g_Wfl);
    cudaGetSymbolAddress((void**)&dWihh_, g_dWihh); cudaGetSymbolAddress((void**)&dWihl_, g_dWihl);
    cudaGetSymbolAddress((void**)&dWhhh_, g_dWhhh); cudaGetSymbolAddress((void**)&dWhhl_, g_dWhhl);
    cudaGetSymbolAddress((void**)&Wdch, g_Wdch); cudaGetSymbolAddress((void**)&Wdcl, g_Wdcl);
    cudaGetSymbolAddress((void**)&eWihh_, g_eWihh); cudaGetSymbolAddress((void**)&eWihl_, g_eWihl);
    cudaGetSymbolAddress((void**)&eWhhh_, g_eWhhh); cudaGetSymbolAddress((void**)&eWhhl_, g_eWhhl);
    cudaGetSymbolAddress((void**)&f16, g_f16);
    cudaGetSymbolAddress((void**)&h16a, g_h16a);
    cudaGetSymbolAddress((void**)&h16b, g_h16b);
    cudaGetSymbolAddress((void**)&d16, g_d16);

    cudaFuncSetAttribute(tgemm, cudaFuncAttributeMaxDynamicSharedMemorySize, TG_SMEM);

    const dim3 blk(256);
    cvt_h<<<NROWS * INDIM / 8 / 256, blk>>>(x, x16, NROWS * INDIM);
    cvt_wpair<<<FDIM * INDIM / 4 / 256, blk>>>(Wf, Wfh, Wfl, FDIM * INDIM);
    cvt_wpair_perm<<<4 * HDIM * FDIM / 4 / 256, blk>>>(dWih, dWihh_, dWihl_, HDIM, FDIM, 4 * HDIM * FDIM);
    cvt_wpair_perm<<<4 * HDIM * HDIM / 4 / 256, blk>>>(dWhh, dWhhh_, dWhhl_, HDIM, HDIM, 4 * HDIM * HDIM);
    cvt_wpair<<<FDIM * HDIM / 4 / 256, blk>>>(Wdc, Wdch, Wdcl, FDIM * HDIM);
    cvt_wpair_perm<<<4 * FDIM * FDIM / 4 / 256, blk>>>(eWih, eWihh_, eWihl_, FDIM, FDIM, 4 * FDIM * FDIM);
    cvt_wpair_perm<<<4 * FDIM * FDIM / 4 / 256, blk>>>(eWhh, eWhhh_, eWhhl_, FDIM, FDIM, 4 * FDIM * FDIM);
    bias_perm<<<(4 * HDIM + 255) / 256, blk>>>(dbih, dbhh, bsd, HDIM);
    bias_perm<<<(4 * FDIM + 255) / 256, blk>>>(ebih, ebhh, bse, FDIM);

    // feats = relu(x @ Wf^T + bf) -> f16 only
    tgemm<<<dim3(FDIM / 256, NROWS / 128), blk, TG_SMEM>>>(
        x16, INDIM, Wfh, Wfl, INDIM, INDIM / 64,
        nullptr, 0, nullptr, nullptr, 0, 0,
        bf_, nullptr, 0, f16, FDIM, 1.0f, 1,
        0, nullptr, nullptr, nullptr, nullptr, 0);

    // decoder: 8 recurrent steps; fused cell with DOUBLE-BUFFERED h16
    // (read-buffer != write-buffer eliminates the cross-CTA race on h16)
    for (int d = 0; d < DSTEPS; d++) {
        const __half* inp   = (d == 0) ? f16 : d16;
        __half* h16_write = (d & 1) ? h16b : h16a;
        const __half* h16_read = (d & 1) ? h16a : h16b;   // prev step's write buffer
        tgemm<<<dim3(4 * HDIM / 256, NROWS / 128), blk, TG_SMEM>>>(
            inp, FDIM, dWihh_, dWihl_, FDIM, FDIM / 64,
            (d > 0) ? h16_read : nullptr, HDIM,
            dWhhh_, dWhhl_, HDIM, (d > 0) ? HDIM / 64 : 0,
            bsd, nullptr, 0, nullptr, 0, 1.0f, 0,
            1, c, c, h16_write, nullptr, d == 0 ? 1 : 0);
        tgemm<<<dim3(FDIM / 256, NROWS / 128), blk, TG_SMEM>>>(
            h16_write, HDIM, Wdch, Wdcl, HDIM, HDIM / 64,
            nullptr, 0, nullptr, nullptr, 0, 0,
            bdc, dec + (size_t)d * FDIM, DSTEPS * FDIM,
            d16, FDIM, (d == DSTEPS - 1) ? (1.0f / DSTEPS) : 1.0f, 0,
            0, nullptr, nullptr, nullptr, nullptr, 0);
    }

    // encoder: fused cell; writes fp32 h for the final projection
    tgemm<<<dim3(4 * FDIM / 256, NROWS / 128), blk, TG_SMEM>>>(
        f16, FDIM, eWihh_, eWihl_, FDIM, FDIM / 64,
        d16, FDIM, eWhhh_, eWhhl_, FDIM, FDIM / 64,
        bse, nullptr, 0, nullptr, 0, 1.0f, 0,
        2, nullptr, nullptr, nullptr, h, 1);
    gemm_tn<<<dim3((CDIM + 127) / 128, NROWS / 128), blk>>>(
        h, FDIM, Wec, FDIM, bec, out, CDIM, NROWS, CDIM, FDIM);
}

// round 7
// speedup vs baseline: 1.7080x; 1.7080x over previous
#include <cuda_runtime.h>
#include <cuda_fp16.h>
#include <stdint.h>
#include <math.h>

// B=64, T=64, D=8, F=1024, H=1024, C=22, IN=4096, N=B*T=4096
#define NROWS 4096
#define FDIM  1024
#define HDIM  1024
#define INDIM 4096
#define DSTEPS 8
#define CDIM  22

// ---------------- scratch (device globals) ----------------------------------
__device__ float g_h[NROWS * HDIM];          // encoder h (fp32)
__device__ float g_c[NROWS * HDIM];          // decoder cell state
__device__ float g_bsum_dec[4 * HDIM];       // gate-interleaved bias
__device__ float g_bsum_enc[4 * FDIM];

__device__ __align__(256) __half g_x16[NROWS * INDIM];
__device__ __align__(256) __half g_Wfh[FDIM * INDIM],  g_Wfl[FDIM * INDIM];
__device__ __align__(256) __half g_dWihh[4 * HDIM * FDIM], g_dWihl[4 * HDIM * FDIM];
__device__ __align__(256) __half g_dWhhh[4 * HDIM * HDIM], g_dWhhl[4 * HDIM * HDIM];
__device__ __align__(256) __half g_Wdch[FDIM * HDIM],  g_Wdcl[FDIM * HDIM];
__device__ __align__(256) __half g_eWihh[4 * FDIM * FDIM], g_eWihl[4 * FDIM * FDIM];
__device__ __align__(256) __half g_eWhhh[4 * FDIM * FDIM], g_eWhhl[4 * FDIM * FDIM];
__device__ __align__(256) __half g_f16[NROWS * FDIM];
__device__ __align__(256) __half g_h16a[NROWS * HDIM];   // double-buffered hidden
__device__ __align__(256) __half g_h16b[NROWS * HDIM];
__device__ __align__(256) __half g_d16[NROWS * FDIM];

// ---------------- PTX helpers ------------------------------------------------
__device__ __forceinline__ uint32_t smem_u32(const void* p) {
    uint32_t a;
    asm("{ .reg .u64 t; cvta.to.shared.u64 t, %1; cvt.u32.u64 %0, t; }" : "=r"(a) : "l"(p));
    return a;
}
__device__ __forceinline__ void cpa16(uint32_t sa, const void* g) {
    asm volatile("cp.async.cg.shared.global [%0], [%1], 16;" :: "r"(sa), "l"(g));
}
__device__ __forceinline__ void cp_commit() {
    asm volatile("cp.async.commit_group;" ::: "memory");
}
template<int N> __device__ __forceinline__ void cp_wait() {
    asm volatile("cp.async.wait_group %0;" :: "n"(N) : "memory");
}
__device__ __forceinline__ void ldmx4(uint32_t* r, uint32_t addr) {
    asm volatile("ldmatrix.sync.aligned.m8n8.x4.shared.b16 {%0,%1,%2,%3}, [%4];"
                 : "=r"(r[0]), "=r"(r[1]), "=r"(r[2]), "=r"(r[3]) : "r"(addr));
}
__device__ __forceinline__ void mma16816(float* c, const uint32_t* a, const uint32_t* b) {
    asm volatile("mma.sync.aligned.m16n8k16.row.col.f32.f16.f16.f32 "
                 "{%0,%1,%2,%3}, {%4,%5,%6,%7}, {%8,%9}, {%0,%1,%2,%3};"
                 : "+f"(c[0]), "+f"(c[1]), "+f"(c[2]), "+f"(c[3])
                 : "r"(a[0]), "r"(a[1]), "r"(a[2]), "r"(a[3]), "r"(b[0]), "r"(b[1]));
}
__device__ __forceinline__ uint32_t swz(int row, int g) {
    return (uint32_t)(row * 128 + ((g ^ (row & 7)) << 4));
}
// register-light fast transcendentals (branch-free; err ~1e-6, well inside budget)
__device__ __forceinline__ float fsig(float x) {
    return __fdividef(1.0f, 1.0f + __expf(-x));
}
__device__ __forceinline__ float ftanh(float x) {
    float t = __expf(2.0f * x);
    return __fdividef(t - 1.0f, t + 1.0f);
}

// ---------------- tensor GEMM ------------------------------------------------
// C[128,256] tile = A[128,K]fp16 @ (B_hi + B_lo)[256,K]^T over two K-sources.
// cell=0: plain epilogue (bias/relu/C/fp16-E).
// cell!=0: LSTM cell fused via smem-staged gates (gate-interleaved columns).
#define T_A  0
#define T_BH 16384
#define T_BL 49152
#define STAGE_SZ 81920
#define TG_SMEM (2 * STAGE_SZ)
#define SROW 260   // padded fp32 staging row (floats)

__global__ __launch_bounds__(256, 1)
void tgemm(const __half* __restrict__ A1, int lda1,
           const __half* __restrict__ B1h, const __half* __restrict__ B1l, int ldb1, int nk1,
           const __half* __restrict__ A2, int lda2,
           const __half* __restrict__ B2h, const __half* __restrict__ B2l, int ldb2, int nk2,
           const float* __restrict__ bias, float* __restrict__ C, int ldc,
           __half* __restrict__ E, int lde, float escale, int relu,
           int cell, const float* __restrict__ cin, float* __restrict__ cout,
           __half* __restrict__ h16o, float* __restrict__ hfo, int czero)
{
    extern __shared__ __align__(1024) char sm[];
    const int tid = threadIdx.x;
    const int wid = tid >> 5;
    const int lane = tid & 31;
    const int wm = wid >> 2;
    const int wn = wid & 3;
    const int bm = blockIdx.y * 128;
    const int bn = blockIdx.x * 256;
    const uint32_t smb = smem_u32(sm);
    const int total = nk1 + nk2;

    float acc[4][8][4];
#pragma unroll
    for (int i = 0; i < 4; i++)
#pragma unroll
        for (int j = 0; j < 8; j++)
#pragma unroll
            for (int k = 0; k < 4; k++) acc[i][j][k] = 0.0f;

    auto load_stage = [&](int q, int s) {
        const __half *a, *bh, *bl; int la, lb, k0;
        if (q < nk1) { a = A1; bh = B1h; bl = B1l; la = lda1; lb = ldb1; k0 = q * 64; }
        else         { a = A2; bh = B2h; bl = B2l; la = lda2; lb = ldb2; k0 = (q - nk1) * 64; }
        const uint32_t sb = smb + (uint32_t)s * STAGE_SZ;
#pragma unroll
        for (int i = 0; i < 4; i++) {
            int v = tid + i * 256;
            int row = v >> 3, g = v & 7;
            cpa16(sb + T_A + swz(row, g), a + (size_t)(bm + row) * la + k0 + g * 8);
        }
#pragma unroll
        for (int i = 0; i < 8; i++) {
            int v = tid + i * 256;
            int row = v >> 3, g = v & 7;
            uint32_t so = swz(row, g);
            cpa16(sb + T_BH + so, bh + (size_t)(bn + row) * lb + k0 + g * 8);
            cpa16(sb + T_BL + so, bl + (size_t)(bn + row) * lb + k0 + g * 8);
        }
        cp_commit();
    };

    const int r8 = lane & 7;
    const int arow0 = wm * 64 + r8 + 8 * ((lane >> 3) & 1);
    const int akq   = lane >> 4;
    const int brow0 = wn * 64 + r8 + 8 * (lane >> 4);
    const int bkq   = (lane >> 3) & 1;

    load_stage(0, 0);

    for (int q = 0; q < total; q++) {
        const int s = q & 1;
        if (q + 1 < total) { load_stage(q + 1, s ^ 1); cp_wait<1>(); }
        else               { cp_wait<0>(); }
        __syncthreads();

        const uint32_t sb = smb + (uint32_t)s * STAGE_SZ;
#pragma unroll
        for (int ks = 0; ks < 4; ks++) {
            uint32_t a[4][4];
#pragma unroll
            for (int mt = 0; mt < 4; mt++)
                ldmx4(a[mt], sb + T_A + swz(arow0 + mt * 16, ks * 2 + akq));
            {
                uint32_t b[8][2];
#pragma unroll
                for (int p = 0; p < 4; p++) {
                    uint32_t t[4];
                    ldmx4(t, sb + T_BH + swz(brow0 + p * 16, ks * 2 + bkq));
                    b[2 * p][0] = t[0]; b[2 * p][1] = t[1];
                    b[2 * p + 1][0] = t[2]; b[2 * p + 1][1] = t[3];
                }
#pragma unroll
                for (int mt = 0; mt < 4; mt++)
#pragma unroll
                    for (int nt = 0; nt < 8; nt++)
                        mma16816(acc[mt][nt], a[mt], b[nt]);
            }
            {
                uint32_t b[8][2];
#pragma unroll
                for (int p = 0; p < 4; p++) {
                    uint32_t t[4];
                    ldmx4(t, sb + T_BL + swz(brow0 + p * 16, ks * 2 + bkq));
                    b[2 * p][0] = t[0]; b[2 * p][1] = t[1];
                    b[2 * p + 1][0] = t[2]; b[2 * p + 1][1] = t[3];
                }
#pragma unroll
                for (int mt = 0; mt < 4; mt++)
#pragma unroll
                    for (int nt = 0; nt < 8; nt++)
                        mma16816(acc[mt][nt], a[mt], b[nt]);
            }
        }
        __syncthreads();
    }

    if (cell == 0) {
        // ---- plain epilogue (proven round-4 path) ----
#pragma unroll
        for (int mt = 0; mt < 4; mt++) {
#pragma unroll
            for (int nt = 0; nt < 8; nt++) {
                const int row = bm + wm * 64 + mt * 16 + (lane >> 2);
                const int col = bn + wn * 64 + nt * 8 + (lane & 3) * 2;
#pragma unroll
                for (int hh2 = 0; hh2 < 2; hh2++) {
                    const int rr = row + hh2 * 8;
                    float v0 = acc[mt][nt][2 * hh2];
                    float v1 = acc[mt][nt][2 * hh2 + 1];
                    if (bias) { v0 += bias[col]; v1 += bias[col + 1]; }
                    if (relu) { v0 = fmaxf(v0, 0.0f); v1 = fmaxf(v1, 0.0f); }
                    if (C)
                        *reinterpret_cast<float2*>(C + (size_t)rr * ldc + col) = make_float2(v0, v1);
                    if (E) {
                        __half2 hp;
                        hp.x = __float2half_rn(v0 * escale);
                        hp.y = __float2half_rn(v1 * escale);
                        *reinterpret_cast<__half2*>(E + (size_t)rr * lde + col) = hp;
                    }
                }
            }
        }
    } else {
        // ---- fused LSTM cell: stage gates tile through smem ----
        // (all stage buffers are dead past the final __syncthreads above)
        float* sg = reinterpret_cast<float*>(sm);
#pragma unroll
        for (int mt = 0; mt < 4; mt++) {
#pragma unroll
            for (int nt = 0; nt < 8; nt++) {
                const int rL = wm * 64 + mt * 16 + (lane >> 2);
                const int cL = wn * 64 + nt * 8 + (lane & 3) * 2;
                const int cG = bn + cL;
#pragma unroll
                for (int hh2 = 0; hh2 < 2; hh2++) {
                    float v0 = acc[mt][nt][2 * hh2]     + bias[cG];
                    float v1 = acc[mt][nt][2 * hh2 + 1] + bias[cG + 1];
                    *reinterpret_cast<float2*>(&sg[(rL + hh2 * 8) * SROW + cL]) =
                        make_float2(v0, v1);
                }
            }
        }
        __syncthreads();
        // unit-major pass: thread handles unit u over 32 rows (stride 4)
        const int u  = tid & 63;           // unit within tile (64 units = 256 gate cols)
        const int rg = tid >> 6;           // 0..3
        const int jG = (bn >> 2) + u;      // global unit index
#pragma unroll 4
        for (int k = 0; k < 32; k++) {
            const int rL = 4 * k + rg;
            float4 gv = *reinterpret_cast<const float4*>(&sg[rL * SROW + u * 4]);
            const size_t oidx = (size_t)(bm + rL) * HDIM + jG;
            float cprev = czero ? 0.0f : cin[oidx];
            float cn = fsig(gv.y) * cprev + fsig(gv.x) * ftanh(gv.z);
            float hn = fsig(gv.w) * ftanh(cn);
            if (cout) cout[oidx] = cn;
            if (h16o) h16o[oidx] = __float2half_rn(hn);
            if (hfo)  hfo[oidx] = hn;
        }
    }
}

// ---------------- SIMT GEMM for tiny N=22 ------------------------------------
__global__ __launch_bounds__(256, 2)
void gemm_tn(const float* __restrict__ A, int lda,
             const float* __restrict__ B, int ldb,
             const float* __restrict__ bias,
             float* __restrict__ C, int ldc,
             int M, int N, int K)
{
    __shared__ float As[16][132];
    __shared__ float Bs[16][132];
    const int tid = threadIdx.x;
    const int bm = blockIdx.y * 128;
    const int bn = blockIdx.x * 128;
    const int tm = (tid >> 4) << 3;
    const int tn = (tid & 15) << 3;
    const int lr = tid >> 2;
    const int lc = (tid & 3) << 2;

    float acc[8][8];
#pragma unroll
    for (int i = 0; i < 8; i++)
#pragma unroll
        for (int j = 0; j < 8; j++) acc[i][j] = 0.0f;

    for (int k0 = 0; k0 < K; k0 += 16) {
#pragma unroll
        for (int h2 = 0; h2 < 2; h2++) {
            int r = lr + h2 * 64;
            const float4 v = *reinterpret_cast<const float4*>(&A[(size_t)(bm + r) * lda + k0 + lc]);
            As[lc + 0][r] = v.x; As[lc + 1][r] = v.y;
            As[lc + 2][r] = v.z; As[lc + 3][r] = v.w;
        }
#pragma unroll
        for (int h2 = 0; h2 < 2; h2++) {
            int r = lr + h2 * 64;
            float4 v = make_float4(0.f, 0.f, 0.f, 0.f);
            if (bn + r < N)
                v = *reinterpret_cast<const float4*>(&B[(size_t)(bn + r) * ldb + k0 + lc]);
            Bs[lc + 0][r] = v.x; Bs[lc + 1][r] = v.y;
            Bs[lc + 2][r] = v.z; Bs[lc + 3][r] = v.w;
        }
        __syncthreads();
#pragma unroll
        for (int k = 0; k < 16; k++) {
            float a[8], b[8];
            *reinterpret_cast<float4*>(&a[0]) = *reinterpret_cast<const float4*>(&As[k][tm]);
            *reinterpret_cast<float4*>(&a[4]) = *reinterpret_cast<const float4*>(&As[k][tm + 4]);
            *reinterpret_cast<float4*>(&b[0]) = *reinterpret_cast<const float4*>(&Bs[k][tn]);
            *reinterpret_cast<float4*>(&b[4]) = *reinterpret_cast<const float4*>(&Bs[k][tn + 4]);
#pragma unroll
            for (int i = 0; i < 8; i++)
#pragma unroll
                for (int j = 0; j < 8; j++)
                    acc[i][j] += a[i] * b[j];
        }
        __syncthreads();
    }
#pragma unroll
    for (int i = 0; i < 8; i++) {
        const int row = bm + tm + i;
        float* crow = C + (size_t)row * ldc;
#pragma unroll
        for (int j = 0; j < 8; j++) {
            const int col = bn + tn + j;
            if (col < N) {
                float v = acc[i][j];
                if (bias) v += bias[col];
                crow[col] = v;
            }
        }
    }
}

// ---------------- conversion kernels -----------------------------------------
__global__ void bias_perm(const float* __restrict__ a, const float* __restrict__ b,
                          float* __restrict__ out, int H)
{
    int i = blockIdx.x * blockDim.x + threadIdx.x;
    if (i >= 4 * H) return;
    int gate = i / H, unit = i - gate * H;
    out[unit * 4 + gate] = a[i] + b[i];
}

__global__ void cvt_wpair(const float* __restrict__ src,
                          __half* __restrict__ hi, __half* __restrict__ lo, int n)
{
    int i = (blockIdx.x * blockDim.x + threadIdx.x) * 4;
    if (i >= n) return;
    float4 v = *reinterpret_cast<const float4*>(src + i);
    float f[4] = { v.x, v.y, v.z, v.w };
    __half h[4], l[4];
#pragma unroll
    for (int k = 0; k < 4; k++) {
        h[k] = __float2half_rn(f[k]);
        l[k] = __float2half_rn(f[k] - __half2float(h[k]));
    }
    __half2 hp0; hp0.x = h[0]; hp0.y = h[1];
    __half2 hp1; hp1.x = h[2]; hp1.y = h[3];
    __half2 lp0; lp0.x = l[0]; lp0.y = l[1];
    __half2 lp1; lp1.x = l[2]; lp1.y = l[3];
    *reinterpret_cast<__half2*>(hi + i) = hp0;
    *reinterpret_cast<__half2*>(hi + i + 2) = hp1;
    *reinterpret_cast<__half2*>(lo + i) = lp0;
    *reinterpret_cast<__half2*>(lo + i + 2) = lp1;
}

__global__ void cvt_wpair_perm(const float* __restrict__ src,
                               __half* __restrict__ hi, __half* __restrict__ lo,
                               int H, int K, int n)
{
    int i = (blockIdx.x * blockDim.x + threadIdx.x) * 4;
    if (i >= n) return;
    int r = i / K, k = i - r * K;
    int gate = r / H, unit = r - gate * H;
    int o = (unit * 4 + gate) * K + k;
    float4 v = *reinterpret_cast<const float4*>(src + i);
    float f[4] = { v.x, v.y, v.z, v.w };
    __half h[4], l[4];
#pragma unroll
    for (int kk = 0; kk < 4; kk++) {
        h[kk] = __float2half_rn(f[kk]);
        l[kk] = __float2half_rn(f[kk] - __half2float(h[kk]));
    }
    __half2 hp0; hp0.x = h[0]; hp0.y = h[1];
    __half2 hp1; hp1.x = h[2]; hp1.y = h[3];
    __half2 lp0; lp0.x = l[0]; lp0.y = l[1];
    __half2 lp1; lp1.x = l[2]; lp1.y = l[3];
    *reinterpret_cast<__half2*>(hi + o) = hp0;
    *reinterpret_cast<__half2*>(hi + o + 2) = hp1;
    *reinterpret_cast<__half2*>(lo + o) = lp0;
    *reinterpret_cast<__half2*>(lo + o + 2) = lp1;
}

__global__ void cvt_h(const float* __restrict__ src, __half* __restrict__ dst, int n)
{
    int i = (blockIdx.x * blockDim.x + threadIdx.x) * 8;
    if (i >= n) return;
    float4 v0 = *reinterpret_cast<const float4*>(src + i);
    float4 v1 = *reinterpret_cast<const float4*>(src + i + 4);
    __half2 p0; p0.x = __float2half_rn(v0.x); p0.y = __float2half_rn(v0.y);
    __half2 p1; p1.x = __float2half_rn(v0.z); p1.y = __float2half_rn(v0.w);
    __half2 p2; p2.x = __float2half_rn(v1.x); p2.y = __float2half_rn(v1.y);
    __half2 p3; p3.x = __float2half_rn(v1.z); p3.y = __float2half_rn(v1.w);
    *reinterpret_cast<__half2*>(dst + i) = p0;
    *reinterpret_cast<__half2*>(dst + i + 2) = p1;
    *reinterpret_cast<__half2*>(dst + i + 4) = p2;
    *reinterpret_cast<__half2*>(dst + i + 6) = p3;
}

// ---------------- launch -----------------------------------------------------
extern "C" void kernel_launch(void* const* d_in, const int* in_sizes, int n_in,
                              void* d_out, int out_size)
{
    const float* x    = (const float*)d_in[0];
    const float* Wf   = (const float*)d_in[1];
    const float* bf_  = (const float*)d_in[2];
    const float* dWih = (const float*)d_in[3];
    const float* dWhh = (const float*)d_in[4];
    const float* dbih = (const float*)d_in[5];
    const float* dbhh = (const float*)d_in[6];
    const float* Wdc  = (const float*)d_in[7];
    const float* bdc  = (const float*)d_in[8];
    const float* eWih = (const float*)d_in[9];
    const float* eWhh = (const float*)d_in[10];
    const float* ebih = (const float*)d_in[11];
    const float* ebhh = (const float*)d_in[12];
    const float* Wec  = (const float*)d_in[13];
    const float* bec  = (const float*)d_in[14];

    float* out = (float*)d_out;
    float* dec = out + 64 * 64 * CDIM;

    float *h, *c, *bsd, *bse;
    __half *x16, *Wfh, *Wfl, *dWihh_, *dWihl_, *dWhhh_, *dWhhl_, *Wdch, *Wdcl;
    __half *eWihh_, *eWihl_, *eWhhh_, *eWhhl_, *f16, *h16a, *h16b, *d16;
    cudaGetSymbolAddress((void**)&h, g_h);
    cudaGetSymbolAddress((void**)&c, g_c);
    cudaGetSymbolAddress((void**)&bsd, g_bsum_dec);
    cudaGetSymbolAddress((void**)&bse, g_bsum_enc);
    cudaGetSymbolAddress((void**)&x16, g_x16);
    cudaGetSymbolAddress((void**)&Wfh, g_Wfh); cudaGetSymbolAddress((void**)&Wfl, g_Wfl);
    cudaGetSymbolAddress((void**)&dWihh_, g_dWihh); cudaGetSymbolAddress((void**)&dWihl_, g_dWihl);
    cudaGetSymbolAddress((void**)&dWhhh_, g_dWhhh); cudaGetSymbolAddress((void**)&dWhhl_, g_dWhhl);
    cudaGetSymbolAddress((void**)&Wdch, g_Wdch); cudaGetSymbolAddress((void**)&Wdcl, g_Wdcl);
    cudaGetSymbolAddress((void**)&eWihh_, g_eWihh); cudaGetSymbolAddress((void**)&eWihl_, g_eWihl);
    cudaGetSymbolAddress((void**)&eWhhh_, g_eWhhh); cudaGetSymbolAddress((void**)&eWhhl_, g_eWhhl);
    cudaGetSymbolAddress((void**)&f16, g_f16);
    cudaGetSymbolAddress((void**)&h16a, g_h16a);
    cudaGetSymbolAddress((void**)&h16b, g_h16b);
    cudaGetSymbolAddress((void**)&d16, g_d16);

    cudaFuncSetAttribute(tgemm, cudaFuncAttributeMaxDynamicSharedMemorySize, TG_SMEM);

    const dim3 blk(256);
    cvt_h<<<NROWS * INDIM / 8 / 256, blk>>>(x, x16, NROWS * INDIM);
    cvt_wpair<<<FDIM * INDIM / 4 / 256, blk>>>(Wf, Wfh, Wfl, FDIM * INDIM);
    cvt_wpair_perm<<<4 * HDIM * FDIM / 4 / 256, blk>>>(dWih, dWihh_, dWihl_, HDIM, FDIM, 4 * HDIM * FDIM);
    cvt_wpair_perm<<<4 * HDIM * HDIM / 4 / 256, blk>>>(dWhh, dWhhh_, dWhhl_, HDIM, HDIM, 4 * HDIM * HDIM);
    cvt_wpair<<<FDIM * HDIM / 4 / 256, blk>>>(Wdc, Wdch, Wdcl, FDIM * HDIM);
    cvt_wpair_perm<<<4 * FDIM * FDIM / 4 / 256, blk>>>(eWih, eWihh_, eWihl_, FDIM, FDIM, 4 * FDIM * FDIM);
    cvt_wpair_perm<<<4 * FDIM * FDIM / 4 / 256, blk>>>(eWhh, eWhhh_, eWhhl_, FDIM, FDIM, 4 * FDIM * FDIM);
    bias_perm<<<(4 * HDIM + 255) / 256, blk>>>(dbih, dbhh, bsd, HDIM);
    bias_perm<<<(4 * FDIM + 255) / 256, blk>>>(ebih, ebhh, bse, FDIM);

    // feats = relu(x @ Wf^T + bf) -> f16 only
    tgemm<<<dim3(FDIM / 256, NROWS / 128), blk, TG_SMEM>>>(
        x16, INDIM, Wfh, Wfl, INDIM, INDIM / 64,
        nullptr, 0, nullptr, nullptr, 0, 0,
        bf_, nullptr, 0, f16, FDIM, 1.0f, 1,
        0, nullptr, nullptr, nullptr, nullptr, 0);

    // decoder: 8 recurrent steps; fused cell, double-buffered h16 (race-free)
    for (int d = 0; d < DSTEPS; d++) {
        const __half* inp   = (d == 0) ? f16 : d16;
        __half* h16_write = (d & 1) ? h16b : h16a;
        const __half* h16_read = (d & 1) ? h16a : h16b;
        tgemm<<<dim3(4 * HDIM / 256, NROWS / 128), blk, TG_SMEM>>>(
            inp, FDIM, dWihh_, dWihl_, FDIM, FDIM / 64,
            (d > 0) ? h16_read : nullptr, HDIM,
            dWhhh_, dWhhl_, HDIM, (d > 0) ? HDIM / 64 : 0,
            bsd, nullptr, 0, nullptr, 0, 1.0f, 0,
            1, c, c, h16_write, nullptr, d == 0 ? 1 : 0);
        tgemm<<<dim3(FDIM / 256, NROWS / 128), blk, TG_SMEM>>>(
            h16_write, HDIM, Wdch, Wdcl, HDIM, HDIM / 64,
            nullptr, 0, nullptr, nullptr, 0, 0,
            bdc, dec + (size_t)d * FDIM, DSTEPS * FDIM,
            d16, FDIM, (d == DSTEPS - 1) ? (1.0f / DSTEPS) : 1.0f, 0,
            0, nullptr, nullptr, nullptr, nullptr, 0);
    }

    // encoder: fused cell; writes fp32 h for the final projection
    tgemm<<<dim3(4 * FDIM / 256, NROWS / 128), blk, TG_SMEM>>>(
        f16, FDIM, eWihh_, eWihl_, FDIM, FDIM / 64,
        d16, FDIM, eWhhh_, eWhhl_, FDIM, FDIM / 64,
        bse, nullptr, 0, nullptr, 0, 1.0f, 0,
        2, nullptr, nullptr, nullptr, h, 1);
    gemm_tn<<<dim3((CDIM + 127) / 128, NROWS / 128), blk>>>(
        h, FDIM, Wec, FDIM, bec, out, CDIM, NROWS, CDIM, FDIM);
}

// round 8
// speedup vs baseline: 2.4036x; 1.4073x over previous
#include <cuda_runtime.h>
#include <cuda_fp16.h>
#include <stdint.h>
#include <math.h>

// B=64, T=64, D=8, F=1024, H=1024, C=22, IN=4096, N=B*T=4096
#define NROWS 4096
#define FDIM  1024
#define HDIM  1024
#define INDIM 4096
#define DSTEPS 8
#define CDIM  22

// ---------------- scratch (device globals) ----------------------------------
__device__ float g_h[NROWS * HDIM];          // P scratch (setup), then encoder h
__device__ float g_c[NROWS * HDIM];          // decoder cell state
__device__ float g_bsum_dec[4 * HDIM];       // gate-interleaved bias (dec)
__device__ float g_bsum_enc[4 * FDIM];       // gate-interleaved bias (enc)
__device__ float g_bcomb[4 * HDIM];          // combined bias: bsd + Wih@bdc

__device__ __align__(256) __half g_x16[NROWS * INDIM];
__device__ __align__(256) __half g_Wfh[FDIM * INDIM],  g_Wfl[FDIM * INDIM];
__device__ __align__(256) __half g_dWihh[4 * HDIM * FDIM], g_dWihl[4 * HDIM * FDIM];
__device__ __align__(256) __half g_Wdch[FDIM * HDIM],  g_Wdcl[FDIM * HDIM];
__device__ __align__(256) __half g_WdcTh[HDIM * FDIM], g_WdcTl[HDIM * FDIM];
__device__ __align__(256) __half g_Wch[4 * HDIM * HDIM], g_Wcl[4 * HDIM * HDIM];
__device__ __align__(256) __half g_eWihh[4 * FDIM * FDIM], g_eWihl[4 * FDIM * FDIM];
__device__ __align__(256) __half g_eWhhh[4 * FDIM * FDIM], g_eWhhl[4 * FDIM * FDIM];
__device__ __align__(256) __half g_f16[NROWS * FDIM];
__device__ __align__(256) __half g_h16a[NROWS * HDIM];   // double-buffered hidden
__device__ __align__(256) __half g_h16b[NROWS * HDIM];
__device__ __align__(256) __half g_d16[NROWS * FDIM];

// ---------------- PTX helpers ------------------------------------------------
__device__ __forceinline__ uint32_t smem_u32(const void* p) {
    uint32_t a;
    asm("{ .reg .u64 t; cvta.to.shared.u64 t, %1; cvt.u32.u64 %0, t; }" : "=r"(a) : "l"(p));
    return a;
}
__device__ __forceinline__ void cpa16(uint32_t sa, const void* g) {
    asm volatile("cp.async.cg.shared.global [%0], [%1], 16;" :: "r"(sa), "l"(g));
}
__device__ __forceinline__ void cp_commit() {
    asm volatile("cp.async.commit_group;" ::: "memory");
}
template<int N> __device__ __forceinline__ void cp_wait() {
    asm volatile("cp.async.wait_group %0;" :: "n"(N) : "memory");
}
__device__ __forceinline__ void ldmx4(uint32_t* r, uint32_t addr) {
    asm volatile("ldmatrix.sync.aligned.m8n8.x4.shared.b16 {%0,%1,%2,%3}, [%4];"
                 : "=r"(r[0]), "=r"(r[1]), "=r"(r[2]), "=r"(r[3]) : "r"(addr));
}
__device__ __forceinline__ void mma16816(float* c, const uint32_t* a, const uint32_t* b) {
    asm volatile("mma.sync.aligned.m16n8k16.row.col.f32.f16.f16.f32 "
                 "{%0,%1,%2,%3}, {%4,%5,%6,%7}, {%8,%9}, {%0,%1,%2,%3};"
                 : "+f"(c[0]), "+f"(c[1]), "+f"(c[2]), "+f"(c[3])
                 : "r"(a[0]), "r"(a[1]), "r"(a[2]), "r"(a[3]), "r"(b[0]), "r"(b[1]));
}
__device__ __forceinline__ uint32_t swz(int row, int g) {
    return (uint32_t)(row * 128 + ((g ^ (row & 7)) << 4));
}
__device__ __forceinline__ float fsig(float x) {
    return __fdividef(1.0f, 1.0f + __expf(-x));
}
__device__ __forceinline__ float ftanh(float x) {
    float t = __expf(2.0f * x);
    return __fdividef(t - 1.0f, t + 1.0f);
}

// ---------------- tensor GEMM ------------------------------------------------
#define T_A  0
#define T_BH 16384
#define T_BL 49152
#define STAGE_SZ 81920
#define TG_SMEM (2 * STAGE_SZ)
#define SROW 260

__global__ __launch_bounds__(256, 1)
void tgemm(const __half* __restrict__ A1, int lda1,
           const __half* __restrict__ B1h, const __half* __restrict__ B1l, int ldb1, int nk1,
           const __half* __restrict__ A2, int lda2,
           const __half* __restrict__ B2h, const __half* __restrict__ B2l, int ldb2, int nk2,
           const float* __restrict__ bias, float* __restrict__ C, int ldc,
           __half* __restrict__ E, int lde, float escale, int relu,
           int cell, const float* __restrict__ cin, float* __restrict__ cout,
           __half* __restrict__ h16o, float* __restrict__ hfo, int czero)
{
    extern __shared__ __align__(1024) char sm[];
    const int tid = threadIdx.x;
    const int wid = tid >> 5;
    const int lane = tid & 31;
    const int wm = wid >> 2;
    const int wn = wid & 3;
    const int bm = blockIdx.y * 128;
    const int bn = blockIdx.x * 256;
    const uint32_t smb = smem_u32(sm);
    const int total = nk1 + nk2;

    float acc[4][8][4];
#pragma unroll
    for (int i = 0; i < 4; i++)
#pragma unroll
        for (int j = 0; j < 8; j++)
#pragma unroll
            for (int k = 0; k < 4; k++) acc[i][j][k] = 0.0f;

    auto load_stage = [&](int q, int s) {
        const __half *a, *bh, *bl; int la, lb, k0;
        if (q < nk1) { a = A1; bh = B1h; bl = B1l; la = lda1; lb = ldb1; k0 = q * 64; }
        else         { a = A2; bh = B2h; bl = B2l; la = lda2; lb = ldb2; k0 = (q - nk1) * 64; }
        const uint32_t sb = smb + (uint32_t)s * STAGE_SZ;
#pragma unroll
        for (int i = 0; i < 4; i++) {
            int v = tid + i * 256;
            int row = v >> 3, g = v & 7;
            cpa16(sb + T_A + swz(row, g), a + (size_t)(bm + row) * la + k0 + g * 8);
        }
#pragma unroll
        for (int i = 0; i < 8; i++) {
            int v = tid + i * 256;
            int row = v >> 3, g = v & 7;
            uint32_t so = swz(row, g);
            cpa16(sb + T_BH + so, bh + (size_t)(bn + row) * lb + k0 + g * 8);
            cpa16(sb + T_BL + so, bl + (size_t)(bn + row) * lb + k0 + g * 8);
        }
        cp_commit();
    };

    const int r8 = lane & 7;
    const int arow0 = wm * 64 + r8 + 8 * ((lane >> 3) & 1);
    const int akq   = lane >> 4;
    const int brow0 = wn * 64 + r8 + 8 * (lane >> 4);
    const int bkq   = (lane >> 3) & 1;

    load_stage(0, 0);

    for (int q = 0; q < total; q++) {
        const int s = q & 1;
        if (q + 1 < total) { load_stage(q + 1, s ^ 1); cp_wait<1>(); }
        else               { cp_wait<0>(); }
        __syncthreads();

        const uint32_t sb = smb + (uint32_t)s * STAGE_SZ;
#pragma unroll
        for (int ks = 0; ks < 4; ks++) {
            uint32_t a[4][4];
#pragma unroll
            for (int mt = 0; mt < 4; mt++)
                ldmx4(a[mt], sb + T_A + swz(arow0 + mt * 16, ks * 2 + akq));
            {
                uint32_t b[8][2];
#pragma unroll
                for (int p = 0; p < 4; p++) {
                    uint32_t t[4];
                    ldmx4(t, sb + T_BH + swz(brow0 + p * 16, ks * 2 + bkq));
                    b[2 * p][0] = t[0]; b[2 * p][1] = t[1];
                    b[2 * p + 1][0] = t[2]; b[2 * p + 1][1] = t[3];
                }
#pragma unroll
                for (int mt = 0; mt < 4; mt++)
#pragma unroll
                    for (int nt = 0; nt < 8; nt++)
                        mma16816(acc[mt][nt], a[mt], b[nt]);
            }
            {
                uint32_t b[8][2];
#pragma unroll
                for (int p = 0; p < 4; p++) {
                    uint32_t t[4];
                    ldmx4(t, sb + T_BL + swz(brow0 + p * 16, ks * 2 + bkq));
                    b[2 * p][0] = t[0]; b[2 * p][1] = t[1];
                    b[2 * p + 1][0] = t[2]; b[2 * p + 1][1] = t[3];
                }
#pragma unroll
                for (int mt = 0; mt < 4; mt++)
#pragma unroll
                    for (int nt = 0; nt < 8; nt++)
                        mma16816(acc[mt][nt], a[mt], b[nt]);
            }
        }
        __syncthreads();
    }

    if (cell == 0) {
        // ---- plain epilogue ----
#pragma unroll
        for (int mt = 0; mt < 4; mt++) {
#pragma unroll
            for (int nt = 0; nt < 8; nt++) {
                const int row = bm + wm * 64 + mt * 16 + (lane >> 2);
                const int col = bn + wn * 64 + nt * 8 + (lane & 3) * 2;
#pragma unroll
                for (int hh2 = 0; hh2 < 2; hh2++) {
                    const int rr = row + hh2 * 8;
                    float v0 = acc[mt][nt][2 * hh2];
                    float v1 = acc[mt][nt][2 * hh2 + 1];
                    if (bias) { v0 += bias[col]; v1 += bias[col + 1]; }
                    if (relu) { v0 = fmaxf(v0, 0.0f); v1 = fmaxf(v1, 0.0f); }
                    if (C)
                        *reinterpret_cast<float2*>(C + (size_t)rr * ldc + col) = make_float2(v0, v1);
                    if (E) {
                        __half2 hp;
                        hp.x = __float2half_rn(v0 * escale);
                        hp.y = __float2half_rn(v1 * escale);
                        *reinterpret_cast<__half2*>(E + (size_t)rr * lde + col) = hp;
                    }
                }
            }
        }
    } else {
        // ---- fused LSTM cell via smem-staged gates ----
        float* sg = reinterpret_cast<float*>(sm);
#pragma unroll
        for (int mt = 0; mt < 4; mt++) {
#pragma unroll
            for (int nt = 0; nt < 8; nt++) {
                const int rL = wm * 64 + mt * 16 + (lane >> 2);
                const int cL = wn * 64 + nt * 8 + (lane & 3) * 2;
                const int cG = bn + cL;
#pragma unroll
                for (int hh2 = 0; hh2 < 2; hh2++) {
                    float v0 = acc[mt][nt][2 * hh2]     + bias[cG];
                    float v1 = acc[mt][nt][2 * hh2 + 1] + bias[cG + 1];
                    *reinterpret_cast<float2*>(&sg[(rL + hh2 * 8) * SROW + cL]) =
                        make_float2(v0, v1);
                }
            }
        }
        __syncthreads();
        const int u  = tid & 63;
        const int rg = tid >> 6;
        const int jG = (bn >> 2) + u;
#pragma unroll 4
        for (int k = 0; k < 32; k++) {
            const int rL = 4 * k + rg;
            float4 gv = *reinterpret_cast<const float4*>(&sg[rL * SROW + u * 4]);
            const size_t oidx = (size_t)(bm + rL) * HDIM + jG;
            float cprev = czero ? 0.0f : cin[oidx];
            float cn = fsig(gv.y) * cprev + fsig(gv.x) * ftanh(gv.z);
            float hn = fsig(gv.w) * ftanh(cn);
            if (cout) cout[oidx] = cn;
            if (h16o) h16o[oidx] = __float2half_rn(hn);
            if (hfo)  hfo[oidx] = hn;
        }
    }
}

// ---------------- SIMT GEMM for tiny N=22 ------------------------------------
__global__ __launch_bounds__(256, 2)
void gemm_tn(const float* __restrict__ A, int lda,
             const float* __restrict__ B, int ldb,
             const float* __restrict__ bias,
             float* __restrict__ C, int ldc,
             int M, int N, int K)
{
    __shared__ float As[16][132];
    __shared__ float Bs[16][132];
    const int tid = threadIdx.x;
    const int bm = blockIdx.y * 128;
    const int bn = blockIdx.x * 128;
    const int tm = (tid >> 4) << 3;
    const int tn = (tid & 15) << 3;
    const int lr = tid >> 2;
    const int lc = (tid & 3) << 2;

    float acc[8][8];
#pragma unroll
    for (int i = 0; i < 8; i++)
#pragma unroll
        for (int j = 0; j < 8; j++) acc[i][j] = 0.0f;

    for (int k0 = 0; k0 < K; k0 += 16) {
#pragma unroll
        for (int h2 = 0; h2 < 2; h2++) {
            int r = lr + h2 * 64;
            const float4 v = *reinterpret_cast<const float4*>(&A[(size_t)(bm + r) * lda + k0 + lc]);
            As[lc + 0][r] = v.x; As[lc + 1][r] = v.y;
            As[lc + 2][r] = v.z; As[lc + 3][r] = v.w;
        }
#pragma unroll
        for (int h2 = 0; h2 < 2; h2++) {
            int r = lr + h2 * 64;
            float4 v = make_float4(0.f, 0.f, 0.f, 0.f);
            if (bn + r < N)
                v = *reinterpret_cast<const float4*>(&B[(size_t)(bn + r) * ldb + k0 + lc]);
            Bs[lc + 0][r] = v.x; Bs[lc + 1][r] = v.y;
            Bs[lc + 2][r] = v.z; Bs[lc + 3][r] = v.w;
        }
        __syncthreads();
#pragma unroll
        for (int k = 0; k < 16; k++) {
            float a[8], b[8];
            *reinterpret_cast<float4*>(&a[0]) = *reinterpret_cast<const float4*>(&As[k][tm]);
            *reinterpret_cast<float4*>(&a[4]) = *reinterpret_cast<const float4*>(&As[k][tm + 4]);
            *reinterpret_cast<float4*>(&b[0]) = *reinterpret_cast<const float4*>(&Bs[k][tn]);
            *reinterpret_cast<float4*>(&b[4]) = *reinterpret_cast<const float4*>(&Bs[k][tn + 4]);
#pragma unroll
            for (int i = 0; i < 8; i++)
#pragma unroll
                for (int j = 0; j < 8; j++)
                    acc[i][j] += a[i] * b[j];
        }
        __syncthreads();
    }
#pragma unroll
    for (int i = 0; i < 8; i++) {
        const int row = bm + tm + i;
        float* crow = C + (size_t)row * ldc;
#pragma unroll
        for (int j = 0; j < 8; j++) {
            const int col = bn + tn + j;
            if (col < N) {
                float v = acc[i][j];
                if (bias) v += bias[col];
                crow[col] = v;
            }
        }
    }
}

// ---------------- conversion / setup kernels ---------------------------------
__global__ void bias_perm(const float* __restrict__ a, const float* __restrict__ b,
                          float* __restrict__ out, int H)
{
    int i = blockIdx.x * blockDim.x + threadIdx.x;
    if (i >= 4 * H) return;
    int gate = i / H, unit = i - gate * H;
    out[unit * 4 + gate] = a[i] + b[i];
}

__global__ void cvt_wpair(const float* __restrict__ src,
                          __half* __restrict__ hi, __half* __restrict__ lo, int n)
{
    int i = (blockIdx.x * blockDim.x + threadIdx.x) * 4;
    if (i >= n) return;
    float4 v = *reinterpret_cast<const float4*>(src + i);
    float f[4] = { v.x, v.y, v.z, v.w };
    __half h[4], l[4];
#pragma unroll
    for (int k = 0; k < 4; k++) {
        h[k] = __float2half_rn(f[k]);
        l[k] = __float2half_rn(f[k] - __half2float(h[k]));
    }
    __half2 hp0; hp0.x = h[0]; hp0.y = h[1];
    __half2 hp1; hp1.x = h[2]; hp1.y = h[3];
    __half2 lp0; lp0.x = l[0]; lp0.y = l[1];
    __half2 lp1; lp1.x = l[2]; lp1.y = l[3];
    *reinterpret_cast<__half2*>(hi + i) = hp0;
    *reinterpret_cast<__half2*>(hi + i + 2) = hp1;
    *reinterpret_cast<__half2*>(lo + i) = lp0;
    *reinterpret_cast<__half2*>(lo + i + 2) = lp1;
}

__global__ void cvt_wpair_perm(const float* __restrict__ src,
                               __half* __restrict__ hi, __half* __restrict__ lo,
                               int H, int K, int n)
{
    int i = (blockIdx.x * blockDim.x + threadIdx.x) * 4;
    if (i >= n) return;
    int r = i / K, k = i - r * K;
    int gate = r / H, unit = r - gate * H;
    int o = (unit * 4 + gate) * K + k;
    float4 v = *reinterpret_cast<const float4*>(src + i);
    float f[4] = { v.x, v.y, v.z, v.w };
    __half h[4], l[4];
#pragma unroll
    for (int kk = 0; kk < 4; kk++) {
        h[kk] = __float2half_rn(f[kk]);
        l[kk] = __float2half_rn(f[kk] - __half2float(h[kk]));
    }
    __half2 hp0; hp0.x = h[0]; hp0.y = h[1];
    __half2 hp1; hp1.x = h[2]; hp1.y = h[3];
    __half2 lp0; lp0.x = l[0]; lp0.y = l[1];
    __half2 lp1; lp1.x = l[2]; lp1.y = l[3];
    *reinterpret_cast<__half2*>(hi + o) = hp0;
    *reinterpret_cast<__half2*>(hi + o + 2) = hp1;
    *reinterpret_cast<__half2*>(lo + o) = lp0;
    *reinterpret_cast<__half2*>(lo + o + 2) = lp1;
}

// transposed split: out[j*F + k] = split(src[k*H + j]), src is Wdc [F, H]
__global__ void cvt_wpair_T(const float* __restrict__ src,
                            __half* __restrict__ hi, __half* __restrict__ lo,
                            int F, int H)
{
    int o = blockIdx.x * blockDim.x + threadIdx.x;
    if (o >= F * H) return;
    int j = o / F, k = o - j * F;
    float v = src[(size_t)k * H + j];
    __half h = __float2half_rn(v);
    hi[o] = h;
    lo[o] = __float2half_rn(v - __half2float(h));
}

// Wcomb = P + dWhh(permuted rows); emit hi/lo split
__global__ void cvt_add_pair(const float* __restrict__ P, const float* __restrict__ Whh,
                             __half* __restrict__ hi, __half* __restrict__ lo, int H)
{
    int o = blockIdx.x * blockDim.x + threadIdx.x;
    if (o >= 4 * H * H) return;
    int r = o / H, j = o - r * H;
    int unit = r >> 2, gate = r & 3;
    float v = P[o] + Whh[(size_t)(gate * H + unit) * H + j];
    __half h = __float2half_rn(v);
    hi[o] = h;
    lo[o] = __float2half_rn(v - __half2float(h));
}

// bcomb[r'] = bsd[r'] + dot(dWih row orig(r'), bdc); one warp per row
__global__ void bias_comb(const float* __restrict__ bsd, const float* __restrict__ Wih,
                          const float* __restrict__ bdc, float* __restrict__ out,
                          int H, int K)
{
    int w = (blockIdx.x * blockDim.x + threadIdx.x) >> 5;
    int lane = threadIdx.x & 31;
    if (w >= 4 * H) return;
    int unit = w >> 2, gate = w & 3;
    const float* row = Wih + (size_t)(gate * H + unit) * K;
    float s = 0.0f;
    for (int k = lane; k < K; k += 32) s += row[k] * bdc[k];
#pragma unroll
    for (int off = 16; off; off >>= 1) s += __shfl_xor_sync(0xffffffffu, s, off);
    if (lane == 0) out[w] = bsd[w] + s;
}

__global__ void cvt_h(const float* __restrict__ src, __half* __restrict__ dst, int n)
{
    int i = (blockIdx.x * blockDim.x + threadIdx.x) * 8;
    if (i >= n) return;
    float4 v0 = *reinterpret_cast<const float4*>(src + i);
    float4 v1 = *reinterpret_cast<const float4*>(src + i + 4);
    __half2 p0; p0.x = __float2half_rn(v0.x); p0.y = __float2half_rn(v0.y);
    __half2 p1; p1.x = __float2half_rn(v0.z); p1.y = __float2half_rn(v0.w);
    __half2 p2; p2.x = __float2half_rn(v1.x); p2.y = __float2half_rn(v1.y);
    __half2 p3; p3.x = __float2half_rn(v1.z); p3.y = __float2half_rn(v1.w);
    *reinterpret_cast<__half2*>(dst + i) = p0;
    *reinterpret_cast<__half2*>(dst + i + 2) = p1;
    *reinterpret_cast<__half2*>(dst + i + 4) = p2;
    *reinterpret_cast<__half2*>(dst + i + 6) = p3;
}

// ---------------- launch -----------------------------------------------------
extern "C" void kernel_launch(void* const* d_in, const int* in_sizes, int n_in,
                              void* d_out, int out_size)
{
    const float* x    = (const float*)d_in[0];
    const float* Wf   = (const float*)d_in[1];
    const float* bf_  = (const float*)d_in[2];
    const float* dWih = (const float*)d_in[3];
    const float* dWhh = (const float*)d_in[4];
    const float* dbih = (const float*)d_in[5];
    const float* dbhh = (const float*)d_in[6];
    const float* Wdc  = (const float*)d_in[7];
    const float* bdc  = (const float*)d_in[8];
    const float* eWih = (const float*)d_in[9];
    const float* eWhh = (const float*)d_in[10];
    const float* ebih = (const float*)d_in[11];
    const float* ebhh = (const float*)d_in[12];
    const float* Wec  = (const float*)d_in[13];
    const float* bec  = (const float*)d_in[14];

    float* out = (float*)d_out;
    float* dec = out + 64 * 64 * CDIM;

    float *h, *c, *bsd, *bse, *bcomb;
    __half *x16, *Wfh, *Wfl, *dWihh_, *dWihl_, *Wdch, *Wdcl, *WdcTh, *WdcTl, *Wch, *Wcl;
    __half *eWihh_, *eWihl_, *eWhhh_, *eWhhl_, *f16, *h16a, *h16b, *d16;
    cudaGetSymbolAddress((void**)&h, g_h);
    cudaGetSymbolAddress((void**)&c, g_c);
    cudaGetSymbolAddress((void**)&bsd, g_bsum_dec);
    cudaGetSymbolAddress((void**)&bse, g_bsum_enc);
    cudaGetSymbolAddress((void**)&bcomb, g_bcomb);
    cudaGetSymbolAddress((void**)&x16, g_x16);
    cudaGetSymbolAddress((void**)&Wfh, g_Wfh); cudaGetSymbolAddress((void**)&Wfl, g_Wfl);
    cudaGetSymbolAddress((void**)&dWihh_, g_dWihh); cudaGetSymbolAddress((void**)&dWihl_, g_dWihl);
    cudaGetSymbolAddress((void**)&Wdch, g_Wdch); cudaGetSymbolAddress((void**)&Wdcl, g_Wdcl);
    cudaGetSymbolAddress((void**)&WdcTh, g_WdcTh); cudaGetSymbolAddress((void**)&WdcTl, g_WdcTl);
    cudaGetSymbolAddress((void**)&Wch, g_Wch); cudaGetSymbolAddress((void**)&Wcl, g_Wcl);
    cudaGetSymbolAddress((void**)&eWihh_, g_eWihh); cudaGetSymbolAddress((void**)&eWihl_, g_eWihl);
    cudaGetSymbolAddress((void**)&eWhhh_, g_eWhhh); cudaGetSymbolAddress((void**)&eWhhl_, g_eWhhl);
    cudaGetSymbolAddress((void**)&f16, g_f16);
    cudaGetSymbolAddress((void**)&h16a, g_h16a);
    cudaGetSymbolAddress((void**)&h16b, g_h16b);
    cudaGetSymbolAddress((void**)&d16, g_d16);

    cudaFuncSetAttribute(tgemm, cudaFuncAttributeMaxDynamicSharedMemorySize, TG_SMEM);

    const dim3 blk(256);
    // ---- conversions ----
    cvt_h<<<NROWS * INDIM / 8 / 256, blk>>>(x, x16, NROWS * INDIM);
    cvt_wpair<<<FDIM * INDIM / 4 / 256, blk>>>(Wf, Wfh, Wfl, FDIM * INDIM);
    cvt_wpair_perm<<<4 * HDIM * FDIM / 4 / 256, blk>>>(dWih, dWihh_, dWihl_, HDIM, FDIM, 4 * HDIM * FDIM);
    cvt_wpair<<<FDIM * HDIM / 4 / 256, blk>>>(Wdc, Wdch, Wdcl, FDIM * HDIM);
    cvt_wpair_T<<<(HDIM * FDIM + 255) / 256, blk>>>(Wdc, WdcTh, WdcTl, FDIM, HDIM);
    cvt_wpair_perm<<<4 * FDIM * FDIM / 4 / 256, blk>>>(eWih, eWihh_, eWihl_, FDIM, FDIM, 4 * FDIM * FDIM);
    cvt_wpair_perm<<<4 * FDIM * FDIM / 4 / 256, blk>>>(eWhh, eWhhh_, eWhhl_, FDIM, FDIM, 4 * FDIM * FDIM);
    bias_perm<<<(4 * HDIM + 255) / 256, blk>>>(dbih, dbhh, bsd, HDIM);
    bias_perm<<<(4 * FDIM + 255) / 256, blk>>>(ebih, ebhh, bse, FDIM);
    bias_comb<<<4 * HDIM * 32 / 256, blk>>>(bsd, dWih, bdc, bcomb, HDIM, FDIM);

    // ---- precompute Wcomb = dWih@Wdc + dWhh (P in g_h scratch) ----
    // P = (dWih_hi + dWih_lo) @ WdcT^T   (4-product, ~fp32 accurate)
    tgemm<<<dim3(HDIM / 256, 4 * HDIM / 128), blk, TG_SMEM>>>(
        dWihh_, FDIM, WdcTh, WdcTl, FDIM, FDIM / 64,
        dWihl_, FDIM, WdcTh, WdcTl, FDIM, FDIM / 64,
        nullptr, h, HDIM, nullptr, 0, 1.0f, 0,
        0, nullptr, nullptr, nullptr, nullptr, 0);
    cvt_add_pair<<<(4 * HDIM * HDIM + 255) / 256, blk>>>(h, dWhh, Wch, Wcl, HDIM);

    // ---- feats = relu(x @ Wf^T + bf) -> f16 ----
    tgemm<<<dim3(FDIM / 256, NROWS / 128), blk, TG_SMEM>>>(
        x16, INDIM, Wfh, Wfl, INDIM, INDIM / 64,
        nullptr, 0, nullptr, nullptr, 0, 0,
        bf_, nullptr, 0, f16, FDIM, 1.0f, 1,
        0, nullptr, nullptr, nullptr, nullptr, 0);

    // ---- decoder ----
    // d=0: gates = feats @ dWih^T + bsd (cell, czero)
    tgemm<<<dim3(4 * HDIM / 256, NROWS / 128), blk, TG_SMEM>>>(
        f16, FDIM, dWihh_, dWihl_, FDIM, FDIM / 64,
        nullptr, 0, nullptr, nullptr, 0, 0,
        bsd, nullptr, 0, nullptr, 0, 1.0f, 0,
        1, c, c, h16a, nullptr, 1);
    // dec_out_0 = h0 @ Wdc^T + bdc
    tgemm<<<dim3(FDIM / 256, NROWS / 128), blk, TG_SMEM>>>(
        h16a, HDIM, Wdch, Wdcl, HDIM, HDIM / 64,
        nullptr, 0, nullptr, nullptr, 0, 0,
        bdc, dec, DSTEPS * FDIM, nullptr, 0, 1.0f, 0,
        0, nullptr, nullptr, nullptr, nullptr, 0);

    for (int d = 1; d < DSTEPS; d++) {
        __half* h16_write = (d & 1) ? h16b : h16a;
        const __half* h16_read = (d & 1) ? h16a : h16b;
        // gates = h_{d-1} @ Wcomb^T + bcomb   (K=1024 only!)
        tgemm<<<dim3(4 * HDIM / 256, NROWS / 128), blk, TG_SMEM>>>(
            h16_read, HDIM, Wch, Wcl, HDIM, HDIM / 64,
            nullptr, 0, nullptr, nullptr, 0, 0,
            bcomb, nullptr, 0, nullptr, 0, 1.0f, 0,
            1, c, c, h16_write, nullptr, 0);
        // dec_out_d = h_d @ Wdc^T + bdc (emit d16 only on last step, scaled 1/D)
        tgemm<<<dim3(FDIM / 256, NROWS / 128), blk, TG_SMEM>>>(
            h16_write, HDIM, Wdch, Wdcl, HDIM, HDIM / 64,
            nullptr, 0, nullptr, nullptr, 0, 0,
            bdc, dec + (size_t)d * FDIM, DSTEPS * FDIM,
            (d == DSTEPS - 1) ? d16 : nullptr, FDIM, 1.0f / DSTEPS, 0,
            0, nullptr, nullptr, nullptr, nullptr, 0);
    }

    // ---- encoder ----
    tgemm<<<dim3(4 * FDIM / 256, NROWS / 128), blk, TG_SMEM>>>(
        f16, FDIM, eWihh_, eWihl_, FDIM, FDIM / 64,
        d16, FDIM, eWhhh_, eWhhl_, FDIM, FDIM / 64,
        bse, nullptr, 0, nullptr, 0, 1.0f, 0,
        2, nullptr, nullptr, nullptr, h, 1);
    gemm_tn<<<dim3((CDIM + 127) / 128, NROWS / 128), blk>>>(
        h, FDIM, Wec, FDIM, bec, out, CDIM, NROWS, CDIM, FDIM);
}

// round 10
// speedup vs baseline: 3.6916x; 1.5358x over previous
#include <cuda_runtime.h>
#include <cuda_fp16.h>
#include <stdint.h>
#include <math.h>

// B=64, T=64, D=8, F=1024, H=1024, C=22, IN=4096, N=B*T=4096
#define NROWS 4096
#define FDIM  1024
#define HDIM  1024
#define INDIM 4096
#define DSTEPS 8
#define CDIM  22

// ---------------- scratch (device globals) ----------------------------------
__device__ float g_h[4 * HDIM * HDIM];       // P scratch (setup), then encoder h
__device__ float g_c[NROWS * HDIM];          // decoder cell state
__device__ float g_bsum_dec[4 * HDIM];       // gate-interleaved bias (dec)
__device__ float g_bsum_enc[4 * FDIM];       // gate-interleaved bias (enc)
__device__ float g_bcomb[4 * HDIM];          // combined bias: bsd + Wih@bdc

__device__ __align__(256) __half g_x16[NROWS * INDIM];
__device__ __align__(256) __half g_Wf16[FDIM * INDIM];
__device__ __align__(256) __half g_dWih16[4 * HDIM * FDIM];
__device__ __align__(256) __half g_Wdc16[FDIM * HDIM];
__device__ __align__(256) __half g_WdcT16[HDIM * FDIM];
__device__ __align__(256) __half g_Wc16[4 * HDIM * HDIM];
__device__ __align__(256) __half g_eWih16[4 * FDIM * FDIM];
__device__ __align__(256) __half g_eWhh16[4 * FDIM * FDIM];
__device__ __align__(256) __half g_f16[NROWS * FDIM];
__device__ __align__(256) __half g_h16a[NROWS * HDIM];
__device__ __align__(256) __half g_h16b[NROWS * HDIM];
__device__ __align__(256) __half g_d16[NROWS * FDIM];

// ---------------- PTX helpers ------------------------------------------------
__device__ __forceinline__ uint32_t smem_u32(const void* p) {
    uint32_t a;
    asm("{ .reg .u64 t; cvta.to.shared.u64 t, %1; cvt.u32.u64 %0, t; }" : "=r"(a) : "l"(p));
    return a;
}
__device__ __forceinline__ void cpa16(uint32_t sa, const void* g) {
    asm volatile("cp.async.cg.shared.global [%0], [%1], 16;" :: "r"(sa), "l"(g));
}
__device__ __forceinline__ void cp_commit() {
    asm volatile("cp.async.commit_group;" ::: "memory");
}
template<int N> __device__ __forceinline__ void cp_wait() {
    asm volatile("cp.async.wait_group %0;" :: "n"(N) : "memory");
}
__device__ __forceinline__ void ldmx4(uint32_t* r, uint32_t addr) {
    asm volatile("ldmatrix.sync.aligned.m8n8.x4.shared.b16 {%0,%1,%2,%3}, [%4];"
                 : "=r"(r[0]), "=r"(r[1]), "=r"(r[2]), "=r"(r[3]) : "r"(addr));
}
__device__ __forceinline__ void mma16816(float* c, const uint32_t* a, const uint32_t* b) {
    asm volatile("mma.sync.aligned.m16n8k16.row.col.f32.f16.f16.f32 "
                 "{%0,%1,%2,%3}, {%4,%5,%6,%7}, {%8,%9}, {%0,%1,%2,%3};"
                 : "+f"(c[0]), "+f"(c[1]), "+f"(c[2]), "+f"(c[3])
                 : "r"(a[0]), "r"(a[1]), "r"(a[2]), "r"(a[3]), "r"(b[0]), "r"(b[1]));
}
__device__ __forceinline__ uint32_t swz(int row, int g) {
    return (uint32_t)(row * 128 + ((g ^ (row & 7)) << 4));
}
__device__ __forceinline__ float fsig(float x) {
    return __fdividef(1.0f, 1.0f + __expf(-x));
}
__device__ __forceinline__ float ftanh(float x) {
    float t = __expf(2.0f * x);
    return __fdividef(t - 1.0f, t + 1.0f);
}

// ---------------- tensor GEMM ------------------------------------------------
// C[128,256] tile = A[128,K]fp16 @ B[256,K]^T fp16, two sequential K-sources.
// 3-stage cp.async pipeline. cell=0 plain / cell!=0 fused LSTM via smem staging.
#define T_A  0
#define T_B  16384
#define STAGE_SZ 49152
#define TG_SMEM (3 * STAGE_SZ)
#define SROW 260

__global__ __launch_bounds__(256, 1)
void tgemm(const __half* __restrict__ A1, int lda1,
           const __half* __restrict__ B1, int ldb1, int nk1,
           const __half* __restrict__ A2, int lda2,
           const __half* __restrict__ B2, int ldb2, int nk2,
           const float* __restrict__ bias, float* __restrict__ C, int ldc,
           __half* __restrict__ E, int lde, float escale, int relu,
           int cell, const float* __restrict__ cin, float* __restrict__ cout,
           __half* __restrict__ h16o, float* __restrict__ hfo, int czero)
{
    extern __shared__ __align__(1024) char sm[];
    const int tid = threadIdx.x;
    const int wid = tid >> 5;
    const int lane = tid & 31;
    const int wm = wid >> 2;
    const int wn = wid & 3;
    const int bm = blockIdx.y * 128;
    const int bn = blockIdx.x * 256;
    const uint32_t smb = smem_u32(sm);
    const int total = nk1 + nk2;

    float acc[4][8][4];
#pragma unroll
    for (int i = 0; i < 4; i++)
#pragma unroll
        for (int j = 0; j < 8; j++)
#pragma unroll
            for (int k = 0; k < 4; k++) acc[i][j][k] = 0.0f;

    auto load_stage = [&](int q, int s) {
        const __half *a, *b; int la, lb, k0;
        if (q < nk1) { a = A1; b = B1; la = lda1; lb = ldb1; k0 = q * 64; }
        else         { a = A2; b = B2; la = lda2; lb = ldb2; k0 = (q - nk1) * 64; }
        const uint32_t sb = smb + (uint32_t)s * STAGE_SZ;
#pragma unroll
        for (int i = 0; i < 4; i++) {
            int v = tid + i * 256;
            int row = v >> 3, g = v & 7;
            cpa16(sb + T_A + swz(row, g), a + (size_t)(bm + row) * la + k0 + g * 8);
        }
#pragma unroll
        for (int i = 0; i < 8; i++) {
            int v = tid + i * 256;
            int row = v >> 3, g = v & 7;
            cpa16(sb + T_B + swz(row, g), b + (size_t)(bn + row) * lb + k0 + g * 8);
        }
        cp_commit();
    };

    const int r8 = lane & 7;
    const int arow0 = wm * 64 + r8 + 8 * ((lane >> 3) & 1);
    const int akq   = lane >> 4;
    const int brow0 = wn * 64 + r8 + 8 * (lane >> 4);
    const int bkq   = (lane >> 3) & 1;

    load_stage(0, 0);
    load_stage(1, 1);

    for (int q = 0; q < total; q++) {
        const int s = q % 3;
        if (q + 2 < total) cp_wait<1>();
        else               cp_wait<0>();
        __syncthreads();
        if (q + 2 < total) load_stage(q + 2, (q + 2) % 3);

        const uint32_t sb = smb + (uint32_t)s * STAGE_SZ;
#pragma unroll
        for (int ks = 0; ks < 4; ks++) {
            uint32_t a[4][4];
#pragma unroll
            for (int mt = 0; mt < 4; mt++)
                ldmx4(a[mt], sb + T_A + swz(arow0 + mt * 16, ks * 2 + akq));
            uint32_t b[8][2];
#pragma unroll
            for (int p = 0; p < 4; p++) {
                uint32_t t[4];
                ldmx4(t, sb + T_B + swz(brow0 + p * 16, ks * 2 + bkq));
                b[2 * p][0] = t[0]; b[2 * p][1] = t[1];
                b[2 * p + 1][0] = t[2]; b[2 * p + 1][1] = t[3];
            }
#pragma unroll
            for (int mt = 0; mt < 4; mt++)
#pragma unroll
                for (int nt = 0; nt < 8; nt++)
                    mma16816(acc[mt][nt], a[mt], b[nt]);
        }
        __syncthreads();
    }

    if (cell == 0) {
        // ---- plain epilogue ----
#pragma unroll
        for (int mt = 0; mt < 4; mt++) {
#pragma unroll
            for (int nt = 0; nt < 8; nt++) {
                const int row = bm + wm * 64 + mt * 16 + (lane >> 2);
                const int col = bn + wn * 64 + nt * 8 + (lane & 3) * 2;
#pragma unroll
                for (int hh2 = 0; hh2 < 2; hh2++) {
                    const int rr = row + hh2 * 8;
                    float v0 = acc[mt][nt][2 * hh2];
                    float v1 = acc[mt][nt][2 * hh2 + 1];
                    if (bias) { v0 += bias[col]; v1 += bias[col + 1]; }
                    if (relu) { v0 = fmaxf(v0, 0.0f); v1 = fmaxf(v1, 0.0f); }
                    if (C)
                        *reinterpret_cast<float2*>(C + (size_t)rr * ldc + col) = make_float2(v0, v1);
                    if (E) {
                        __half2 hp;
                        hp.x = __float2half_rn(v0 * escale);
                        hp.y = __float2half_rn(v1 * escale);
                        *reinterpret_cast<__half2*>(E + (size_t)rr * lde + col) = hp;
                    }
                }
            }
        }
    } else {
        // ---- fused LSTM cell via smem-staged gates ----
        float* sg = reinterpret_cast<float*>(sm);
#pragma unroll
        for (int mt = 0; mt < 4; mt++) {
#pragma unroll
            for (int nt = 0; nt < 8; nt++) {
                const int rL = wm * 64 + mt * 16 + (lane >> 2);
                const int cL = wn * 64 + nt * 8 + (lane & 3) * 2;
                const int cG = bn + cL;
#pragma unroll
                for (int hh2 = 0; hh2 < 2; hh2++) {
                    float v0 = acc[mt][nt][2 * hh2]     + bias[cG];
                    float v1 = acc[mt][nt][2 * hh2 + 1] + bias[cG + 1];
                    *reinterpret_cast<float2*>(&sg[(rL + hh2 * 8) * SROW + cL]) =
                        make_float2(v0, v1);
                }
            }
        }
        __syncthreads();
        const int u  = tid & 63;
        const int rg = tid >> 6;
        const int jG = (bn >> 2) + u;
#pragma unroll 4
        for (int k = 0; k < 32; k++) {
            const int rL = 4 * k + rg;
            float4 gv = *reinterpret_cast<const float4*>(&sg[rL * SROW + u * 4]);
            const size_t oidx = (size_t)(bm + rL) * HDIM + jG;
            float cprev = czero ? 0.0f : cin[oidx];
            float cn = fsig(gv.y) * cprev + fsig(gv.x) * ftanh(gv.z);
            float hn = fsig(gv.w) * ftanh(cn);
            if (cout) cout[oidx] = cn;
            if (h16o) h16o[oidx] = __float2half_rn(hn);
            if (hfo)  hfo[oidx] = hn;
        }
    }
}

// ---------------- SIMT GEMM for tiny N=22 ------------------------------------
__global__ __launch_bounds__(256, 2)
void gemm_tn(const float* __restrict__ A, int lda,
             const float* __restrict__ B, int ldb,
             const float* __restrict__ bias,
             float* __restrict__ C, int ldc,
             int M, int N, int K)
{
    __shared__ float As[16][132];
    __shared__ float Bs[16][132];
    const int tid = threadIdx.x;
    const int bm = blockIdx.y * 128;
    const int bn = blockIdx.x * 128;
    const int tm = (tid >> 4) << 3;
    const int tn = (tid & 15) << 3;
    const int lr = tid >> 2;
    const int lc = (tid & 3) << 2;

    float acc[8][8];
#pragma unroll
    for (int i = 0; i < 8; i++)
#pragma unroll
        for (int j = 0; j < 8; j++) acc[i][j] = 0.0f;

    for (int k0 = 0; k0 < K; k0 += 16) {
#pragma unroll
        for (int h2 = 0; h2 < 2; h2++) {
            int r = lr + h2 * 64;
            const float4 v = *reinterpret_cast<const float4*>(&A[(size_t)(bm + r) * lda + k0 + lc]);
            As[lc + 0][r] = v.x; As[lc + 1][r] = v.y;
            As[lc + 2][r] = v.z; As[lc + 3][r] = v.w;
        }
#pragma unroll
        for (int h2 = 0; h2 < 2; h2++) {
            int r = lr + h2 * 64;
            float4 v = make_float4(0.f, 0.f, 0.f, 0.f);
            if (bn + r < N)
                v = *reinterpret_cast<const float4*>(&B[(size_t)(bn + r) * ldb + k0 + lc]);
            Bs[lc + 0][r] = v.x; Bs[lc + 1][r] = v.y;
            Bs[lc + 2][r] = v.z; Bs[lc + 3][r] = v.w;
        }
        __syncthreads();
#pragma unroll
        for (int k = 0; k < 16; k++) {
            float a[8], b[8];
            *reinterpret_cast<float4*>(&a[0]) = *reinterpret_cast<const float4*>(&As[k][tm]);
            *reinterpret_cast<float4*>(&a[4]) = *reinterpret_cast<const float4*>(&As[k][tm + 4]);
            *reinterpret_cast<float4*>(&b[0]) = *reinterpret_cast<const float4*>(&Bs[k][tn]);
            *reinterpret_cast<float4*>(&b[4]) = *reinterpret_cast<const float4*>(&Bs[k][tn + 4]);
#pragma unroll
            for (int i = 0; i < 8; i++)
#pragma unroll
                for (int j = 0; j < 8; j++)
                    acc[i][j] += a[i] * b[j];
        }
        __syncthreads();
    }
#pragma unroll
    for (int i = 0; i < 8; i++) {
        const int row = bm + tm + i;
        float* crow = C + (size_t)row * ldc;
#pragma unroll
        for (int j = 0; j < 8; j++) {
            const int col = bn + tn + j;
            if (col < N) {
                float v = acc[i][j];
                if (bias) v += bias[col];
                crow[col] = v;
            }
        }
    }
}

// ---------------- conversion / setup kernels ---------------------------------
__global__ void bias_perm(const float* __restrict__ a, const float* __restrict__ b,
                          float* __restrict__ out, int H)
{
    int i = blockIdx.x * blockDim.x + threadIdx.x;
    if (i >= 4 * H) return;
    int gate = i / H, unit = i - gate * H;
    out[unit * 4 + gate] = a[i] + b[i];
}

// fp32 -> fp16 (plain)
__global__ void cvt_w(const float* __restrict__ src, __half* __restrict__ dst, int n)
{
    int i = (blockIdx.x * blockDim.x + threadIdx.x) * 8;
    if (i >= n) return;
    float4 v0 = *reinterpret_cast<const float4*>(src + i);
    float4 v1 = *reinterpret_cast<const float4*>(src + i + 4);
    __half2 p0; p0.x = __float2half_rn(v0.x); p0.y = __float2half_rn(v0.y);
    __half2 p1; p1.x = __float2half_rn(v0.z); p1.y = __float2half_rn(v0.w);
    __half2 p2; p2.x = __float2half_rn(v1.x); p2.y = __float2half_rn(v1.y);
    __half2 p3; p3.x = __float2half_rn(v1.z); p3.y = __float2half_rn(v1.w);
    *reinterpret_cast<__half2*>(dst + i) = p0;
    *reinterpret_cast<__half2*>(dst + i + 2) = p1;
    *reinterpret_cast<__half2*>(dst + i + 4) = p2;
    *reinterpret_cast<__half2*>(dst + i + 6) = p3;
}

// weights [4H, K] -> fp16 with gate-interleaved row permute
__global__ void cvt_w_perm(const float* __restrict__ src, __half* __restrict__ dst,
                           int H, int K, int n)
{
    int i = (blockIdx.x * blockDim.x + threadIdx.x) * 4;
    if (i >= n) return;
    int r = i / K, k = i - r * K;
    int gate = r / H, unit = r - gate * H;
    int o = (unit * 4 + gate) * K + k;
    float4 v = *reinterpret_cast<const float4*>(src + i);
    __half2 p0; p0.x = __float2half_rn(v.x); p0.y = __float2half_rn(v.y);
    __half2 p1; p1.x = __float2half_rn(v.z); p1.y = __float2half_rn(v.w);
    *reinterpret_cast<__half2*>(dst + o) = p0;
    *reinterpret_cast<__half2*>(dst + o + 2) = p1;
}

// transposed: out[j*F + k] = fp16(src[k*H + j]), src is Wdc [F, H]
__global__ void cvt_w_T(const float* __restrict__ src, __half* __restrict__ dst,
                        int F, int H)
{
    int o = blockIdx.x * blockDim.x + threadIdx.x;
    if (o >= F * H) return;
    int j = o / F, k = o - j * F;
    dst[o] = __float2half_rn(src[(size_t)k * H + j]);
}

// Wcomb = P + dWhh(permuted rows) -> fp16
__global__ void cvt_add(const float* __restrict__ P, const float* __restrict__ Whh,
                        __half* __restrict__ dst, int H)
{
    int o = blockIdx.x * blockDim.x + threadIdx.x;
    if (o >= 4 * H * H) return;
    int r = o / H, j = o - r * H;
    int unit = r >> 2, gate = r & 3;
    dst[o] = __float2half_rn(P[o] + Whh[(size_t)(gate * H + unit) * H + j]);
}

// bcomb[r'] = bsd[r'] + dot(dWih row orig(r'), bdc); one warp per row
__global__ void bias_comb(const float* __restrict__ bsd, const float* __restrict__ Wih,
                          const float* __restrict__ bdc, float* __restrict__ out,
                          int H, int K)
{
    int w = (blockIdx.x * blockDim.x + threadIdx.x) >> 5;
    int lane = threadIdx.x & 31;
    if (w >= 4 * H) return;
    int unit = w >> 2, gate = w & 3;
    const float* row = Wih + (size_t)(gate * H + unit) * K;
    float s = 0.0f;
    for (int k = lane; k < K; k += 32) s += row[k] * bdc[k];
#pragma unroll
    for (int off = 16; off; off >>= 1) s += __shfl_xor_sync(0xffffffffu, s, off);
    if (lane == 0) out[w] = bsd[w] + s;
}

// ---------------- launch -----------------------------------------------------
extern "C" void kernel_launch(void* const* d_in, const int* in_sizes, int n_in,
                              void* d_out, int out_size)
{
    const float* x    = (const float*)d_in[0];
    const float* Wf   = (const float*)d_in[1];
    const float* bf_  = (const float*)d_in[2];
    const float* dWih = (const float*)d_in[3];
    const float* dWhh = (const float*)d_in[4];
    const float* dbih = (const float*)d_in[5];
    const float* dbhh = (const float*)d_in[6];
    const float* Wdc  = (const float*)d_in[7];
    const float* bdc  = (const float*)d_in[8];
    const float* eWih = (const float*)d_in[9];
    const float* eWhh = (const float*)d_in[10];
    const float* ebih = (const float*)d_in[11];
    const float* ebhh = (const float*)d_in[12];
    const float* Wec  = (const float*)d_in[13];
    const float* bec  = (const float*)d_in[14];

    float* out = (float*)d_out;
    float* dec = out + 64 * 64 * CDIM;

    float *h, *c, *bsd, *bse, *bcomb;
    __half *x16, *Wf16, *dWih16, *Wdc16, *WdcT16, *Wc16, *eWih16, *eWhh16;
    __half *f16, *h16a, *h16b, *d16;
    cudaGetSymbolAddress((void**)&h, g_h);
    cudaGetSymbolAddress((void**)&c, g_c);
    cudaGetSymbolAddress((void**)&bsd, g_bsum_dec);
    cudaGetSymbolAddress((void**)&bse, g_bsum_enc);
    cudaGetSymbolAddress((void**)&bcomb, g_bcomb);
    cudaGetSymbolAddress((void**)&x16, g_x16);
    cudaGetSymbolAddress((void**)&Wf16, g_Wf16);
    cudaGetSymbolAddress((void**)&dWih16, g_dWih16);
    cudaGetSymbolAddress((void**)&Wdc16, g_Wdc16);
    cudaGetSymbolAddress((void**)&WdcT16, g_WdcT16);
    cudaGetSymbolAddress((void**)&Wc16, g_Wc16);
    cudaGetSymbolAddress((void**)&eWih16, g_eWih16);
    cudaGetSymbolAddress((void**)&eWhh16, g_eWhh16);
    cudaGetSymbolAddress((void**)&f16, g_f16);
    cudaGetSymbolAddress((void**)&h16a, g_h16a);
    cudaGetSymbolAddress((void**)&h16b, g_h16b);
    cudaGetSymbolAddress((void**)&d16, g_d16);

    cudaFuncSetAttribute(tgemm, cudaFuncAttributeMaxDynamicSharedMemorySize, TG_SMEM);

    const dim3 blk(256);
    // ---- conversions ----
    cvt_w<<<NROWS * INDIM / 8 / 256, blk>>>(x, x16, NROWS * INDIM);
    cvt_w<<<FDIM * INDIM / 8 / 256, blk>>>(Wf, Wf16, FDIM * INDIM);
    cvt_w_perm<<<4 * HDIM * FDIM / 4 / 256, blk>>>(dWih, dWih16, HDIM, FDIM, 4 * HDIM * FDIM);
    cvt_w<<<FDIM * HDIM / 8 / 256, blk>>>(Wdc, Wdc16, FDIM * HDIM);
    cvt_w_T<<<(HDIM * FDIM + 255) / 256, blk>>>(Wdc, WdcT16, FDIM, HDIM);
    cvt_w_perm<<<4 * FDIM * FDIM / 4 / 256, blk>>>(eWih, eWih16, FDIM, FDIM, 4 * FDIM * FDIM);
    cvt_w_perm<<<4 * FDIM * FDIM / 4 / 256, blk>>>(eWhh, eWhh16, FDIM, FDIM, 4 * FDIM * FDIM);
    bias_perm<<<(4 * HDIM + 255) / 256, blk>>>(dbih, dbhh, bsd, HDIM);
    bias_perm<<<(4 * FDIM + 255) / 256, blk>>>(ebih, ebhh, bse, FDIM);
    bias_comb<<<4 * HDIM * 32 / 256, blk>>>(bsd, dWih, bdc, bcomb, HDIM, FDIM);

    // ---- precompute P = dWih @ Wdc (fp32 out), then Wcomb = P + dWhh -> fp16
    tgemm<<<dim3(HDIM / 256, 4 * HDIM / 128), blk, TG_SMEM>>>(
        dWih16, FDIM, WdcT16, FDIM, FDIM / 64,
        nullptr, 0, nullptr, 0, 0,
        nullptr, h, HDIM, nullptr, 0, 1.0f, 0,
        0, nullptr, nullptr, nullptr, nullptr, 0);
    cvt_add<<<(4 * HDIM * HDIM + 255) / 256, blk>>>(h, dWhh, Wc16, HDIM);

    // ---- feats = relu(x @ Wf^T + bf) -> f16 ----
    tgemm<<<dim3(FDIM / 256, NROWS / 128), blk, TG_SMEM>>>(
        x16, INDIM, Wf16, INDIM, INDIM / 64,
        nullptr, 0, nullptr, 0, 0,
        bf_, nullptr, 0, f16, FDIM, 1.0f, 1,
        0, nullptr, nullptr, nullptr, nullptr, 0);

    // ---- decoder ----
    tgemm<<<dim3(4 * HDIM / 256, NROWS / 128), blk, TG_SMEM>>>(
        f16, FDIM, dWih16, FDIM, FDIM / 64,
        nullptr, 0, nullptr, 0, 0,
        bsd, nullptr, 0, nullptr, 0, 1.0f, 0,
        1, c, c, h16a, nullptr, 1);
    tgemm<<<dim3(FDIM / 256, NROWS / 128), blk, TG_SMEM>>>(
        h16a, HDIM, Wdc16, HDIM, HDIM / 64,
        nullptr, 0, nullptr, 0, 0,
        bdc, dec, DSTEPS * FDIM, nullptr, 0, 1.0f, 0,
        0, nullptr, nullptr, nullptr, nullptr, 0);

    for (int d = 1; d < DSTEPS; d++) {
        __half* h16_write = (d & 1) ? h16b : h16a;
        const __half* h16_read = (d & 1) ? h16a : h16b;
        // gates = h_{d-1} @ Wcomb^T + bcomb (K=1024)
        tgemm<<<dim3(4 * HDIM / 256, NROWS / 128), blk, TG_SMEM>>>(
            h16_read, HDIM, Wc16, HDIM, HDIM / 64,
            nullptr, 0, nullptr, 0, 0,
            bcomb, nullptr, 0, nullptr, 0, 1.0f, 0,
            1, c, c, h16_write, nullptr, 0);
        // dec_out_d = h_d @ Wdc^T + bdc (emit d16 on last step, scaled 1/D)
        tgemm<<<dim3(FDIM / 256, NROWS / 128), blk, TG_SMEM>>>(
            h16_write, HDIM, Wdc16, HDIM, HDIM / 64,
            nullptr, 0, nullptr, 0, 0,
            bdc, dec + (size_t)d * FDIM, DSTEPS * FDIM,
            (d == DSTEPS - 1) ? d16 : nullptr, FDIM, 1.0f / DSTEPS, 0,
            0, nullptr, nullptr, nullptr, nullptr, 0);
    }

    // ---- encoder ----
    tgemm<<<dim3(4 * FDIM / 256, NROWS / 128), blk, TG_SMEM>>>(
        f16, FDIM, eWih16, FDIM, FDIM / 64,
        d16, FDIM, eWhh16, FDIM, FDIM / 64,
        bse, nullptr, 0, nullptr, 0, 1.0f, 0,
        2, nullptr, nullptr, nullptr, h, 1);
    gemm_tn<<<dim3((CDIM + 127) / 128, NROWS / 128), blk>>>(
        h, FDIM, Wec, FDIM, bec, out, CDIM, NROWS, CDIM, FDIM);
}

// round 11
// speedup vs baseline: 3.6982x; 1.0018x over previous
#include <cuda_runtime.h>
#include <cuda_fp16.h>
#include <stdint.h>
#include <math.h>

// B=64, T=64, D=8, F=1024, H=1024, C=22, IN=4096, N=B*T=4096
#define NROWS 4096
#define FDIM  1024
#define HDIM  1024
#define INDIM 4096
#define DSTEPS 8
#define CDIM  22

// ---------------- scratch (device globals) ----------------------------------
__device__ float g_h[4 * HDIM * HDIM];       // P/P2 scratch, then encoder h (16MB)
__device__ float g_c[NROWS * HDIM];          // decoder cell state
__device__ float g_bsum_dec[4 * HDIM];       // gate-interleaved bias (dec)
__device__ float g_bsum_enc[4 * FDIM];       // gate-interleaved bias (enc, unfolded)
__device__ float g_bcomb[4 * HDIM];          // dec combined bias: bsd + dWih@bdc
__device__ float g_benc2[4 * FDIM];          // enc combined bias: bse + eWhh@bdc/D

__device__ __align__(256) __half g_x16[NROWS * INDIM];
__device__ __align__(256) __half g_Wf16[FDIM * INDIM];
__device__ __align__(256) __half g_dWih16[4 * HDIM * FDIM];
__device__ __align__(256) __half g_Wdc16[FDIM * HDIM];
__device__ __align__(256) __half g_WdcT16[HDIM * FDIM];
__device__ __align__(256) __half g_Wc16[4 * HDIM * HDIM];
__device__ __align__(256) __half g_eWih16[4 * FDIM * FDIM];
__device__ __align__(256) __half g_eWhh16[4 * FDIM * FDIM];
__device__ __align__(256) __half g_Wenc16[4 * FDIM * HDIM];
__device__ __align__(256) __half g_f16[NROWS * FDIM];
__device__ __align__(256) __half g_hall[DSTEPS * NROWS * HDIM];  // all h_d (64MB)

// ---------------- PTX helpers ------------------------------------------------
__device__ __forceinline__ uint32_t smem_u32(const void* p) {
    uint32_t a;
    asm("{ .reg .u64 t; cvta.to.shared.u64 t, %1; cvt.u32.u64 %0, t; }" : "=r"(a) : "l"(p));
    return a;
}
__device__ __forceinline__ void cpa16(uint32_t sa, const void* g) {
    asm volatile("cp.async.cg.shared.global [%0], [%1], 16;" :: "r"(sa), "l"(g));
}
__device__ __forceinline__ void cp_commit() {
    asm volatile("cp.async.commit_group;" ::: "memory");
}
template<int N> __device__ __forceinline__ void cp_wait() {
    asm volatile("cp.async.wait_group %0;" :: "n"(N) : "memory");
}
__device__ __forceinline__ void ldmx4(uint32_t* r, uint32_t addr) {
    asm volatile("ldmatrix.sync.aligned.m8n8.x4.shared.b16 {%0,%1,%2,%3}, [%4];"
                 : "=r"(r[0]), "=r"(r[1]), "=r"(r[2]), "=r"(r[3]) : "r"(addr));
}
__device__ __forceinline__ void mma16816(float* c, const uint32_t* a, const uint32_t* b) {
    asm volatile("mma.sync.aligned.m16n8k16.row.col.f32.f16.f16.f32 "
                 "{%0,%1,%2,%3}, {%4,%5,%6,%7}, {%8,%9}, {%0,%1,%2,%3};"
                 : "+f"(c[0]), "+f"(c[1]), "+f"(c[2]), "+f"(c[3])
                 : "r"(a[0]), "r"(a[1]), "r"(a[2]), "r"(a[3]), "r"(b[0]), "r"(b[1]));
}
__device__ __forceinline__ uint32_t swz(int row, int g) {
    return (uint32_t)(row * 128 + ((g ^ (row & 7)) << 4));
}
__device__ __forceinline__ float fsig(float x) {
    return __fdividef(1.0f, 1.0f + __expf(-x));
}
__device__ __forceinline__ float ftanh(float x) {
    float t = __expf(2.0f * x);
    return __fdividef(t - 1.0f, t + 1.0f);
}

// ---------------- tensor GEMM ------------------------------------------------
// C[128,256] tile = A[128,K]fp16 @ B[256,K]^T fp16, two sequential K-sources.
// 3-stage cp.async pipeline. cell=0 plain / cell!=0 fused LSTM.
// decmode: scatter M=[8*4096] rows into dec_scores [N, D, F] layout.
#define T_A  0
#define T_B  16384
#define STAGE_SZ 49152
#define TG_SMEM (3 * STAGE_SZ)
#define SROW 260

__global__ __launch_bounds__(256, 1)
void tgemm(const __half* __restrict__ A1, int lda1,
           const __half* __restrict__ B1, int ldb1, int nk1,
           const __half* __restrict__ A2, int lda2,
           const __half* __restrict__ B2, int ldb2, int nk2,
           const float* __restrict__ bias, float* __restrict__ C, int ldc,
           __half* __restrict__ E, int lde, float escale, int relu,
           int cell, const float* __restrict__ cin, float* __restrict__ cout,
           __half* __restrict__ h16o, float* __restrict__ hfo, int czero,
           int decmode)
{
    extern __shared__ __align__(1024) char sm[];
    const int tid = threadIdx.x;
    const int wid = tid >> 5;
    const int lane = tid & 31;
    const int wm = wid >> 2;
    const int wn = wid & 3;
    const int bm = blockIdx.y * 128;
    const int bn = blockIdx.x * 256;
    const uint32_t smb = smem_u32(sm);
    const int total = nk1 + nk2;

    float acc[4][8][4];
#pragma unroll
    for (int i = 0; i < 4; i++)
#pragma unroll
        for (int j = 0; j < 8; j++)
#pragma unroll
            for (int k = 0; k < 4; k++) acc[i][j][k] = 0.0f;

    auto load_stage = [&](int q, int s) {
        const __half *a, *b; int la, lb, k0;
        if (q < nk1) { a = A1; b = B1; la = lda1; lb = ldb1; k0 = q * 64; }
        else         { a = A2; b = B2; la = lda2; lb = ldb2; k0 = (q - nk1) * 64; }
        const uint32_t sb = smb + (uint32_t)s * STAGE_SZ;
#pragma unroll
        for (int i = 0; i < 4; i++) {
            int v = tid + i * 256;
            int row = v >> 3, g = v & 7;
            cpa16(sb + T_A + swz(row, g), a + (size_t)(bm + row) * la + k0 + g * 8);
        }
#pragma unroll
        for (int i = 0; i < 8; i++) {
            int v = tid + i * 256;
            int row = v >> 3, g = v & 7;
            cpa16(sb + T_B + swz(row, g), b + (size_t)(bn + row) * lb + k0 + g * 8);
        }
        cp_commit();
    };

    const int r8 = lane & 7;
    const int arow0 = wm * 64 + r8 + 8 * ((lane >> 3) & 1);
    const int akq   = lane >> 4;
    const int brow0 = wn * 64 + r8 + 8 * (lane >> 4);
    const int bkq   = (lane >> 3) & 1;

    load_stage(0, 0);
    load_stage(1, 1);

    for (int q = 0; q < total; q++) {
        const int s = q % 3;
        if (q + 2 < total) cp_wait<1>();
        else               cp_wait<0>();
        __syncthreads();
        if (q + 2 < total) load_stage(q + 2, (q + 2) % 3);

        const uint32_t sb = smb + (uint32_t)s * STAGE_SZ;
#pragma unroll
        for (int ks = 0; ks < 4; ks++) {
            uint32_t a[4][4];
#pragma unroll
            for (int mt = 0; mt < 4; mt++)
                ldmx4(a[mt], sb + T_A + swz(arow0 + mt * 16, ks * 2 + akq));
            uint32_t b[8][2];
#pragma unroll
            for (int p = 0; p < 4; p++) {
                uint32_t t[4];
                ldmx4(t, sb + T_B + swz(brow0 + p * 16, ks * 2 + bkq));
                b[2 * p][0] = t[0]; b[2 * p][1] = t[1];
                b[2 * p + 1][0] = t[2]; b[2 * p + 1][1] = t[3];
            }
#pragma unroll
            for (int mt = 0; mt < 4; mt++)
#pragma unroll
                for (int nt = 0; nt < 8; nt++)
                    mma16816(acc[mt][nt], a[mt], b[nt]);
        }
        __syncthreads();
    }

    if (cell == 0) {
        // ---- plain epilogue (decmode scatters into [N, D, F]) ----
#pragma unroll
        for (int mt = 0; mt < 4; mt++) {
#pragma unroll
            for (int nt = 0; nt < 8; nt++) {
                const int row = bm + wm * 64 + mt * 16 + (lane >> 2);
                const int col = bn + wn * 64 + nt * 8 + (lane & 3) * 2;
#pragma unroll
                for (int hh2 = 0; hh2 < 2; hh2++) {
                    const int rr = row + hh2 * 8;
                    float v0 = acc[mt][nt][2 * hh2];
                    float v1 = acc[mt][nt][2 * hh2 + 1];
                    if (bias) { v0 += bias[col]; v1 += bias[col + 1]; }
                    if (relu) { v0 = fmaxf(v0, 0.0f); v1 = fmaxf(v1, 0.0f); }
                    if (C) {
                        float* crow;
                        if (decmode) {
                            int dd = rr >> 12, r2 = rr & 4095;
                            crow = C + (size_t)r2 * (DSTEPS * FDIM) + dd * FDIM;
                        } else {
                            crow = C + (size_t)rr * ldc;
                        }
                        *reinterpret_cast<float2*>(crow + col) = make_float2(v0, v1);
                    }
                    if (E) {
                        __half2 hp;
                        hp.x = __float2half_rn(v0 * escale);
                        hp.y = __float2half_rn(v1 * escale);
                        *reinterpret_cast<__half2*>(E + (size_t)rr * lde + col) = hp;
                    }
                }
            }
        }
    } else {
        // ---- fused LSTM cell via smem-staged gates ----
        float* sg = reinterpret_cast<float*>(sm);
#pragma unroll
        for (int mt = 0; mt < 4; mt++) {
#pragma unroll
            for (int nt = 0; nt < 8; nt++) {
                const int rL = wm * 64 + mt * 16 + (lane >> 2);
                const int cL = wn * 64 + nt * 8 + (lane & 3) * 2;
                const int cG = bn + cL;
#pragma unroll
                for (int hh2 = 0; hh2 < 2; hh2++) {
                    float v0 = acc[mt][nt][2 * hh2]     + bias[cG];
                    float v1 = acc[mt][nt][2 * hh2 + 1] + bias[cG + 1];
                    *reinterpret_cast<float2*>(&sg[(rL + hh2 * 8) * SROW + cL]) =
                        make_float2(v0, v1);
                }
            }
        }
        __syncthreads();
        const int u  = tid & 63;
        const int rg = tid >> 6;
        const int jG = (bn >> 2) + u;
#pragma unroll 4
        for (int k = 0; k < 32; k++) {
            const int rL = 4 * k + rg;
            float4 gv = *reinterpret_cast<const float4*>(&sg[rL * SROW + u * 4]);
            const size_t oidx = (size_t)(bm + rL) * HDIM + jG;
            float cprev = czero ? 0.0f : cin[oidx];
            float cn = fsig(gv.y) * cprev + fsig(gv.x) * ftanh(gv.z);
            float hn = fsig(gv.w) * ftanh(cn);
            if (cout) cout[oidx] = cn;
            if (h16o) h16o[oidx] = __float2half_rn(hn);
            if (hfo)  hfo[oidx] = hn;
        }
    }
}

// ---------------- SIMT GEMM for tiny N=22 ------------------------------------
__global__ __launch_bounds__(256, 2)
void gemm_tn(const float* __restrict__ A, int lda,
             const float* __restrict__ B, int ldb,
             const float* __restrict__ bias,
             float* __restrict__ C, int ldc,
             int M, int N, int K)
{
    __shared__ float As[16][132];
    __shared__ float Bs[16][132];
    const int tid = threadIdx.x;
    const int bm = blockIdx.y * 128;
    const int bn = blockIdx.x * 128;
    const int tm = (tid >> 4) << 3;
    const int tn = (tid & 15) << 3;
    const int lr = tid >> 2;
    const int lc = (tid & 3) << 2;

    float acc[8][8];
#pragma unroll
    for (int i = 0; i < 8; i++)
#pragma unroll
        for (int j = 0; j < 8; j++) acc[i][j] = 0.0f;

    for (int k0 = 0; k0 < K; k0 += 16) {
#pragma unroll
        for (int h2 = 0; h2 < 2; h2++) {
            int r = lr + h2 * 64;
            const float4 v = *reinterpret_cast<const float4*>(&A[(size_t)(bm + r) * lda + k0 + lc]);
            As[lc + 0][r] = v.x; As[lc + 1][r] = v.y;
            As[lc + 2][r] = v.z; As[lc + 3][r] = v.w;
        }
#pragma unroll
        for (int h2 = 0; h2 < 2; h2++) {
            int r = lr + h2 * 64;
            float4 v = make_float4(0.f, 0.f, 0.f, 0.f);
            if (bn + r < N)
                v = *reinterpret_cast<const float4*>(&B[(size_t)(bn + r) * ldb + k0 + lc]);
            Bs[lc + 0][r] = v.x; Bs[lc + 1][r] = v.y;
            Bs[lc + 2][r] = v.z; Bs[lc + 3][r] = v.w;
        }
        __syncthreads();
#pragma unroll
        for (int k = 0; k < 16; k++) {
            float a[8], b[8];
            *reinterpret_cast<float4*>(&a[0]) = *reinterpret_cast<const float4*>(&As[k][tm]);
            *reinterpret_cast<float4*>(&a[4]) = *reinterpret_cast<const float4*>(&As[k][tm + 4]);
            *reinterpret_cast<float4*>(&b[0]) = *reinterpret_cast<const float4*>(&Bs[k][tn]);
            *reinterpret_cast<float4*>(&b[4]) = *reinterpret_cast<const float4*>(&Bs[k][tn + 4]);
#pragma unroll
            for (int i = 0; i < 8; i++)
#pragma unroll
                for (int j = 0; j < 8; j++)
                    acc[i][j] += a[i] * b[j];
        }
        __syncthreads();
    }
#pragma unroll
    for (int i = 0; i < 8; i++) {
        const int row = bm + tm + i;
        float* crow = C + (size_t)row * ldc;
#pragma unroll
        for (int j = 0; j < 8; j++) {
            const int col = bn + tn + j;
            if (col < N) {
                float v = acc[i][j];
                if (bias) v += bias[col];
                crow[col] = v;
            }
        }
    }
}

// ---------------- conversion / setup kernels ---------------------------------
__global__ void bias_perm(const float* __restrict__ a, const float* __restrict__ b,
                          float* __restrict__ out, int H)
{
    int i = blockIdx.x * blockDim.x + threadIdx.x;
    if (i >= 4 * H) return;
    int gate = i / H, unit = i - gate * H;
    out[unit * 4 + gate] = a[i] + b[i];
}

__global__ void cvt_w(const float* __restrict__ src, __half* __restrict__ dst, int n)
{
    int i = (blockIdx.x * blockDim.x + threadIdx.x) * 8;
    if (i >= n) return;
    float4 v0 = *reinterpret_cast<const float4*>(src + i);
    float4 v1 = *reinterpret_cast<const float4*>(src + i + 4);
    __half2 p0; p0.x = __float2half_rn(v0.x); p0.y = __float2half_rn(v0.y);
    __half2 p1; p1.x = __float2half_rn(v0.z); p1.y = __float2half_rn(v0.w);
    __half2 p2; p2.x = __float2half_rn(v1.x); p2.y = __float2half_rn(v1.y);
    __half2 p3; p3.x = __float2half_rn(v1.z); p3.y = __float2half_rn(v1.w);
    *reinterpret_cast<__half2*>(dst + i) = p0;
    *reinterpret_cast<__half2*>(dst + i + 2) = p1;
    *reinterpret_cast<__half2*>(dst + i + 4) = p2;
    *reinterpret_cast<__half2*>(dst + i + 6) = p3;
}

__global__ void cvt_w_perm(const float* __restrict__ src, __half* __restrict__ dst,
                           int H, int K, int n)
{
    int i = (blockIdx.x * blockDim.x + threadIdx.x) * 4;
    if (i >= n) return;
    int r = i / K, k = i - r * K;
    int gate = r / H, unit = r - gate * H;
    int o = (unit * 4 + gate) * K + k;
    float4 v = *reinterpret_cast<const float4*>(src + i);
    __half2 p0; p0.x = __float2half_rn(v.x); p0.y = __float2half_rn(v.y);
    __half2 p1; p1.x = __float2half_rn(v.z); p1.y = __float2half_rn(v.w);
    *reinterpret_cast<__half2*>(dst + o) = p0;
    *reinterpret_cast<__half2*>(dst + o + 2) = p1;
}

__global__ void cvt_w_T(const float* __restrict__ src, __half* __restrict__ dst,
                        int F, int H)
{
    int o = blockIdx.x * blockDim.x + threadIdx.x;
    if (o >= F * H) return;
    int j = o / F, k = o - j * F;
    dst[o] = __float2half_rn(src[(size_t)k * H + j]);
}

// dst = fp16(P + Whh(permuted rows))
__global__ void cvt_add(const float* __restrict__ P, const float* __restrict__ Whh,
                        __half* __restrict__ dst, int H)
{
    int o = blockIdx.x * blockDim.x + threadIdx.x;
    if (o >= 4 * H * H) return;
    int r = o / H, j = o - r * H;
    int unit = r >> 2, gate = r & 3;
    dst[o] = __float2half_rn(P[o] + Whh[(size_t)(gate * H + unit) * H + j]);
}

// dst = fp16(src * scale)
__global__ void cvt_scale(const float* __restrict__ src, __half* __restrict__ dst,
                          float scale, int n)
{
    int i = blockIdx.x * blockDim.x + threadIdx.x;
    if (i < n) dst[i] = __float2half_rn(src[i] * scale);
}

// out[w(perm)] = base[w] + scale * dot(W orig-row, v); one warp per row
__global__ void bias_comb(const float* __restrict__ base, const float* __restrict__ W,
                          const float* __restrict__ v, float* __restrict__ out,
                          int H, int K, float scale)
{
    int w = (blockIdx.x * blockDim.x + threadIdx.x) >> 5;
    int lane = threadIdx.x & 31;
    if (w >= 4 * H) return;
    int unit = w >> 2, gate = w & 3;
    const float* row = W + (size_t)(gate * H + unit) * K;
    float s = 0.0f;
    for (int k = lane; k < K; k += 32) s += row[k] * v[k];
#pragma unroll
    for (int off = 16; off; off >>= 1) s += __shfl_xor_sync(0xffffffffu, s, off);
    if (lane == 0) out[w] = base[w] + s * scale;
}

// ---------------- launch -----------------------------------------------------
extern "C" void kernel_launch(void* const* d_in, const int* in_sizes, int n_in,
                              void* d_out, int out_size)
{
    const float* x    = (const float*)d_in[0];
    const float* Wf   = (const float*)d_in[1];
    const float* bf_  = (const float*)d_in[2];
    const float* dWih = (const float*)d_in[3];
    const float* dWhh = (const float*)d_in[4];
    const float* dbih = (const float*)d_in[5];
    const float* dbhh = (const float*)d_in[6];
    const float* Wdc  = (const float*)d_in[7];
    const float* bdc  = (const float*)d_in[8];
    const float* eWih = (const float*)d_in[9];
    const float* eWhh = (const float*)d_in[10];
    const float* ebih = (const float*)d_in[11];
    const float* ebhh = (const float*)d_in[12];
    const float* Wec  = (const float*)d_in[13];
    const float* bec  = (const float*)d_in[14];

    float* out = (float*)d_out;
    float* dec = out + 64 * 64 * CDIM;

    float *h, *c, *bsd, *bse, *bcomb, *benc2;
    __half *x16, *Wf16, *dWih16, *Wdc16, *WdcT16, *Wc16, *eWih16, *eWhh16, *Wenc16;
    __half *f16, *hall;
    cudaGetSymbolAddress((void**)&h, g_h);
    cudaGetSymbolAddress((void**)&c, g_c);
    cudaGetSymbolAddress((void**)&bsd, g_bsum_dec);
    cudaGetSymbolAddress((void**)&bse, g_bsum_enc);
    cudaGetSymbolAddress((void**)&bcomb, g_bcomb);
    cudaGetSymbolAddress((void**)&benc2, g_benc2);
    cudaGetSymbolAddress((void**)&x16, g_x16);
    cudaGetSymbolAddress((void**)&Wf16, g_Wf16);
    cudaGetSymbolAddress((void**)&dWih16, g_dWih16);
    cudaGetSymbolAddress((void**)&Wdc16, g_Wdc16);
    cudaGetSymbolAddress((void**)&WdcT16, g_WdcT16);
    cudaGetSymbolAddress((void**)&Wc16, g_Wc16);
    cudaGetSymbolAddress((void**)&eWih16, g_eWih16);
    cudaGetSymbolAddress((void**)&eWhh16, g_eWhh16);
    cudaGetSymbolAddress((void**)&Wenc16, g_Wenc16);
    cudaGetSymbolAddress((void**)&f16, g_f16);
    cudaGetSymbolAddress((void**)&hall, g_hall);

    cudaFuncSetAttribute(tgemm, cudaFuncAttributeMaxDynamicSharedMemorySize, TG_SMEM);

    const dim3 blk(256);
    const size_t NH = (size_t)NROWS * HDIM;

    // ---- conversions ----
    cvt_w<<<NROWS * INDIM / 8 / 256, blk>>>(x, x16, NROWS * INDIM);
    cvt_w<<<FDIM * INDIM / 8 / 256, blk>>>(Wf, Wf16, FDIM * INDIM);
    cvt_w_perm<<<4 * HDIM * FDIM / 4 / 256, blk>>>(dWih, dWih16, HDIM, FDIM, 4 * HDIM * FDIM);
    cvt_w<<<FDIM * HDIM / 8 / 256, blk>>>(Wdc, Wdc16, FDIM * HDIM);
    cvt_w_T<<<(HDIM * FDIM + 255) / 256, blk>>>(Wdc, WdcT16, FDIM, HDIM);
    cvt_w_perm<<<4 * FDIM * FDIM / 4 / 256, blk>>>(eWih, eWih16, FDIM, FDIM, 4 * FDIM * FDIM);
    cvt_w_perm<<<4 * FDIM * FDIM / 4 / 256, blk>>>(eWhh, eWhh16, FDIM, FDIM, 4 * FDIM * FDIM);
    bias_perm<<<(4 * HDIM + 255) / 256, blk>>>(dbih, dbhh, bsd, HDIM);
    bias_perm<<<(4 * FDIM + 255) / 256, blk>>>(ebih, ebhh, bse, FDIM);
    bias_comb<<<4 * HDIM * 32 / 256, blk>>>(bsd, dWih, bdc, bcomb, HDIM, FDIM, 1.0f);
    bias_comb<<<4 * FDIM * 32 / 256, blk>>>(bse, eWhh, bdc, benc2, FDIM, FDIM, 1.0f / DSTEPS);

    // ---- precompute Wcomb = dWih@Wdc + dWhh -> fp16 (P in g_h) ----
    tgemm<<<dim3(HDIM / 256, 4 * HDIM / 128), blk, TG_SMEM>>>(
        dWih16, FDIM, WdcT16, FDIM, FDIM / 64,
        nullptr, 0, nullptr, 0, 0,
        nullptr, h, HDIM, nullptr, 0, 1.0f, 0,
        0, nullptr, nullptr, nullptr, nullptr, 0, 0);
    cvt_add<<<(4 * HDIM * HDIM + 255) / 256, blk>>>(h, dWhh, Wc16, HDIM);

    // ---- precompute Wenc = (eWhh@Wdc)/D -> fp16 (P2 in g_h, rows pre-permuted) ----
    tgemm<<<dim3(HDIM / 256, 4 * FDIM / 128), blk, TG_SMEM>>>(
        eWhh16, FDIM, WdcT16, FDIM, FDIM / 64,
        nullptr, 0, nullptr, 0, 0,
        nullptr, h, HDIM, nullptr, 0, 1.0f, 0,
        0, nullptr, nullptr, nullptr, nullptr, 0, 0);
    cvt_scale<<<(4 * FDIM * HDIM + 255) / 256, blk>>>(h, Wenc16, 1.0f / DSTEPS, 4 * FDIM * HDIM);

    // ---- feats = relu(x @ Wf^T + bf) -> f16 ----
    tgemm<<<dim3(FDIM / 256, NROWS / 128), blk, TG_SMEM>>>(
        x16, INDIM, Wf16, INDIM, INDIM / 64,
        nullptr, 0, nullptr, 0, 0,
        bf_, nullptr, 0, f16, FDIM, 1.0f, 1,
        0, nullptr, nullptr, nullptr, nullptr, 0, 0);

    // ---- decoder recurrence: 8 gates GEMMs, h_d -> hall[d] ----
    tgemm<<<dim3(4 * HDIM / 256, NROWS / 128), blk, TG_SMEM>>>(
        f16, FDIM, dWih16, FDIM, FDIM / 64,
        nullptr, 0, nullptr, 0, 0,
        bsd, nullptr, 0, nullptr, 0, 1.0f, 0,
        1, c, c, hall, nullptr, 1, 0);
    for (int d = 1; d < DSTEPS; d++) {
        tgemm<<<dim3(4 * HDIM / 256, NROWS / 128), blk, TG_SMEM>>>(
            hall + (size_t)(d - 1) * NH, HDIM, Wc16, HDIM, HDIM / 64,
            nullptr, 0, nullptr, 0, 0,
            bcomb, nullptr, 0, nullptr, 0, 1.0f, 0,
            1, c, c, hall + (size_t)d * NH, nullptr, 0, 0);
    }

    // ---- encoder: gates = f16@eWih^T + h7@Wenc^T + benc2 (no dec-out dep) ----
    tgemm<<<dim3(4 * FDIM / 256, NROWS / 128), blk, TG_SMEM>>>(
        f16, FDIM, eWih16, FDIM, FDIM / 64,
        hall + (size_t)(DSTEPS - 1) * NH, HDIM, Wenc16, HDIM, HDIM / 64,
        benc2, nullptr, 0, nullptr, 0, 1.0f, 0,
        2, nullptr, nullptr, nullptr, h, 1, 0);
    gemm_tn<<<dim3((CDIM + 127) / 128, NROWS / 128), blk>>>(
        h, FDIM, Wec, FDIM, bec, out, CDIM, NROWS, CDIM, FDIM);

    // ---- batched dec_scores: ALL 8 steps in one GEMM (M = 8*4096) ----
    tgemm<<<dim3(FDIM / 256, DSTEPS * NROWS / 128), blk, TG_SMEM>>>(
        hall, HDIM, Wdc16, HDIM, HDIM / 64,
        nullptr, 0, nullptr, 0, 0,
        bdc, dec, 0, nullptr, 0, 1.0f, 0,
        0, nullptr, nullptr, nullptr, nullptr, 0, 1);
}

// round 12
// speedup vs baseline: 4.0309x; 1.0900x over previous
#include <cuda_runtime.h>
#include <cuda_fp16.h>
#include <stdint.h>
#include <math.h>

// B=64, T=64, D=8, F=1024, H=1024, C=22, IN=4096, N=B*T=4096
#define NROWS 4096
#define FDIM  1024
#define HDIM  1024
#define INDIM 4096
#define DSTEPS 8
#define CDIM  22

// ---------------- scratch (device globals) ----------------------------------
__device__ float g_h[4 * HDIM * HDIM];       // P/P2 scratch, then encoder h
__device__ float g_c[NROWS * HDIM];          // decoder cell state
__device__ float g_bsum_dec[4 * HDIM];
__device__ float g_bsum_enc[4 * FDIM];
__device__ float g_bcomb[4 * HDIM];          // bsd + dWih@bdc
__device__ float g_benc2[4 * FDIM];          // bse + eWhh@bdc/D

__device__ __align__(256) __half g_x16[NROWS * INDIM];
__device__ __align__(256) __half g_Wf16[FDIM * INDIM];
__device__ __align__(256) __half g_dWih16[4 * HDIM * FDIM];
__device__ __align__(256) __half g_Wdc16[FDIM * HDIM];
__device__ __align__(256) __half g_WdcT16[HDIM * FDIM];
__device__ __align__(256) __half g_Wc16[4 * HDIM * HDIM];
__device__ __align__(256) __half g_eWih16[4 * FDIM * FDIM];
__device__ __align__(256) __half g_eWhh16[4 * FDIM * FDIM];
__device__ __align__(256) __half g_Wenc16[4 * FDIM * HDIM];
__device__ __align__(256) __half g_f16[NROWS * FDIM];
__device__ __align__(256) __half g_hall[DSTEPS * NROWS * HDIM];

// ---------------- PTX helpers ------------------------------------------------
__device__ __forceinline__ uint32_t smem_u32(const void* p) {
    uint32_t a;
    asm("{ .reg .u64 t; cvta.to.shared.u64 t, %1; cvt.u32.u64 %0, t; }" : "=r"(a) : "l"(p));
    return a;
}
__device__ __forceinline__ void cpa16(uint32_t sa, const void* g) {
    asm volatile("cp.async.cg.shared.global [%0], [%1], 16;" :: "r"(sa), "l"(g));
}
__device__ __forceinline__ void cp_commit() {
    asm volatile("cp.async.commit_group;" ::: "memory");
}
template<int N> __device__ __forceinline__ void cp_wait() {
    asm volatile("cp.async.wait_group %0;" :: "n"(N) : "memory");
}
__device__ __forceinline__ void ldmx4(uint32_t* r, uint32_t addr) {
    asm volatile("ldmatrix.sync.aligned.m8n8.x4.shared.b16 {%0,%1,%2,%3}, [%4];"
                 : "=r"(r[0]), "=r"(r[1]), "=r"(r[2]), "=r"(r[3]) : "r"(addr));
}
__device__ __forceinline__ void mma16816(float* c, const uint32_t* a, const uint32_t* b) {
    asm volatile("mma.sync.aligned.m16n8k16.row.col.f32.f16.f16.f32 "
                 "{%0,%1,%2,%3}, {%4,%5,%6,%7}, {%8,%9}, {%0,%1,%2,%3};"
                 : "+f"(c[0]), "+f"(c[1]), "+f"(c[2]), "+f"(c[3])
                 : "r"(a[0]), "r"(a[1]), "r"(a[2]), "r"(a[3]), "r"(b[0]), "r"(b[1]));
}
__device__ __forceinline__ uint32_t swz(int row, int g) {
    return (uint32_t)(row * 128 + ((g ^ (row & 7)) << 4));
}
__device__ __forceinline__ float fsig(float x) {
    return __fdividef(1.0f, 1.0f + __expf(-x));
}
__device__ __forceinline__ float ftanh(float x) {
    float t = __expf(2.0f * x);
    return __fdividef(t - 1.0f, t + 1.0f);
}

// ---------------- tensor GEMM ------------------------------------------------
// C[128,256] tile = A[128,K]fp16 @ B[256,K]^T fp16, two sequential K-sources.
// K-chunk = 128 per stage (two 64-wide sub-chunks), 2-stage cp.async pipeline.
// nk counts are in units of 128-wide chunks.
#define T_A   0
#define T_B   32768
#define SUB_A 16384
#define SUB_B 32768
#define STAGE_SZ 98304
#define TG_SMEM (2 * STAGE_SZ)
#define SROW 260

__global__ __launch_bounds__(256, 1)
void tgemm(const __half* __restrict__ A1, int lda1,
           const __half* __restrict__ B1, int ldb1, int nk1,
           const __half* __restrict__ A2, int lda2,
           const __half* __restrict__ B2, int ldb2, int nk2,
           const float* __restrict__ bias, float* __restrict__ C, int ldc,
           __half* __restrict__ E, int lde, float escale, int relu,
           int cell, const float* __restrict__ cin, float* __restrict__ cout,
           __half* __restrict__ h16o, float* __restrict__ hfo, int czero,
           int decmode)
{
    extern __shared__ __align__(1024) char sm[];
    const int tid = threadIdx.x;
    const int wid = tid >> 5;
    const int lane = tid & 31;
    const int wm = wid >> 2;
    const int wn = wid & 3;
    const int bm = blockIdx.y * 128;
    const int bn = blockIdx.x * 256;
    const uint32_t smb = smem_u32(sm);
    const int total = nk1 + nk2;

    float acc[4][8][4];
#pragma unroll
    for (int i = 0; i < 4; i++)
#pragma unroll
        for (int j = 0; j < 8; j++)
#pragma unroll
            for (int k = 0; k < 4; k++) acc[i][j][k] = 0.0f;

    // load one 128-wide K chunk (two 64-wide sub-chunks) into stage s
    auto load_stage = [&](int q, int s) {
        const __half *a, *b; int la, lb, k0;
        if (q < nk1) { a = A1; b = B1; la = lda1; lb = ldb1; k0 = q * 128; }
        else         { a = A2; b = B2; la = lda2; lb = ldb2; k0 = (q - nk1) * 128; }
        const uint32_t sb = smb + (uint32_t)s * STAGE_SZ;
#pragma unroll
        for (int cch = 0; cch < 2; cch++) {
            const int kk = k0 + cch * 64;
#pragma unroll
            for (int i = 0; i < 4; i++) {
                int v = tid + i * 256;
                int row = v >> 3, g = v & 7;
                cpa16(sb + T_A + cch * SUB_A + swz(row, g),
                      a + (size_t)(bm + row) * la + kk + g * 8);
            }
#pragma unroll
            for (int i = 0; i < 8; i++) {
                int v = tid + i * 256;
                int row = v >> 3, g = v & 7;
                cpa16(sb + T_B + cch * SUB_B + swz(row, g),
                      b + (size_t)(bn + row) * lb + kk + g * 8);
            }
        }
        cp_commit();
    };

    const int r8 = lane & 7;
    const int arow0 = wm * 64 + r8 + 8 * ((lane >> 3) & 1);
    const int akq   = lane >> 4;
    const int brow0 = wn * 64 + r8 + 8 * (lane >> 4);
    const int bkq   = (lane >> 3) & 1;

    load_stage(0, 0);

    for (int q = 0; q < total; q++) {
        const int s = q & 1;
        if (q + 1 < total) { load_stage(q + 1, s ^ 1); cp_wait<1>(); }
        else               { cp_wait<0>(); }
        __syncthreads();

        const uint32_t sb = smb + (uint32_t)s * STAGE_SZ;
#pragma unroll
        for (int cch = 0; cch < 2; cch++) {
            const uint32_t ab = sb + T_A + cch * SUB_A;
            const uint32_t bb = sb + T_B + cch * SUB_B;
#pragma unroll
            for (int ks = 0; ks < 4; ks++) {
                uint32_t a[4][4];
#pragma unroll
                for (int mt = 0; mt < 4; mt++)
                    ldmx4(a[mt], ab + swz(arow0 + mt * 16, ks * 2 + akq));
                uint32_t b[8][2];
#pragma unroll
                for (int p = 0; p < 4; p++) {
                    uint32_t t[4];
                    ldmx4(t, bb + swz(brow0 + p * 16, ks * 2 + bkq));
                    b[2 * p][0] = t[0]; b[2 * p][1] = t[1];
                    b[2 * p + 1][0] = t[2]; b[2 * p + 1][1] = t[3];
                }
#pragma unroll
                for (int mt = 0; mt < 4; mt++)
#pragma unroll
                    for (int nt = 0; nt < 8; nt++)
                        mma16816(acc[mt][nt], a[mt], b[nt]);
            }
        }
        __syncthreads();
    }

    if (cell == 0) {
        // ---- plain epilogue (decmode scatters into [N, D, F]) ----
#pragma unroll
        for (int mt = 0; mt < 4; mt++) {
#pragma unroll
            for (int nt = 0; nt < 8; nt++) {
                const int row = bm + wm * 64 + mt * 16 + (lane >> 2);
                const int col = bn + wn * 64 + nt * 8 + (lane & 3) * 2;
#pragma unroll
                for (int hh2 = 0; hh2 < 2; hh2++) {
                    const int rr = row + hh2 * 8;
                    float v0 = acc[mt][nt][2 * hh2];
                    float v1 = acc[mt][nt][2 * hh2 + 1];
                    if (bias) { v0 += bias[col]; v1 += bias[col + 1]; }
                    if (relu) { v0 = fmaxf(v0, 0.0f); v1 = fmaxf(v1, 0.0f); }
                    if (C) {
                        float* crow;
                        if (decmode) {
                            int dd = rr >> 12, r2 = rr & 4095;
                            crow = C + (size_t)r2 * (DSTEPS * FDIM) + dd * FDIM;
                        } else {
                            crow = C + (size_t)rr * ldc;
                        }
                        *reinterpret_cast<float2*>(crow + col) = make_float2(v0, v1);
                    }
                    if (E) {
                        __half2 hp;
                        hp.x = __float2half_rn(v0 * escale);
                        hp.y = __float2half_rn(v1 * escale);
                        *reinterpret_cast<__half2*>(E + (size_t)rr * lde + col) = hp;
                    }
                }
            }
        }
    } else {
        // ---- fused LSTM cell via smem-staged gates ----
        float* sg = reinterpret_cast<float*>(sm);
#pragma unroll
        for (int mt = 0; mt < 4; mt++) {
#pragma unroll
            for (int nt = 0; nt < 8; nt++) {
                const int rL = wm * 64 + mt * 16 + (lane >> 2);
                const int cL = wn * 64 + nt * 8 + (lane & 3) * 2;
                const int cG = bn + cL;
#pragma unroll
                for (int hh2 = 0; hh2 < 2; hh2++) {
                    float v0 = acc[mt][nt][2 * hh2]     + bias[cG];
                    float v1 = acc[mt][nt][2 * hh2 + 1] + bias[cG + 1];
                    *reinterpret_cast<float2*>(&sg[(rL + hh2 * 8) * SROW + cL]) =
                        make_float2(v0, v1);
                }
            }
        }
        __syncthreads();
        const int u  = tid & 63;
        const int rg = tid >> 6;
        const int jG = (bn >> 2) + u;
#pragma unroll 4
        for (int k = 0; k < 32; k++) {
            const int rL = 4 * k + rg;
            float4 gv = *reinterpret_cast<const float4*>(&sg[rL * SROW + u * 4]);
            const size_t oidx = (size_t)(bm + rL) * HDIM + jG;
            float cprev = czero ? 0.0f : cin[oidx];
            float cn = fsig(gv.y) * cprev + fsig(gv.x) * ftanh(gv.z);
            float hn = fsig(gv.w) * ftanh(cn);
            if (cout) cout[oidx] = cn;
            if (h16o) h16o[oidx] = __float2half_rn(hn);
            if (hfo)  hfo[oidx] = hn;
        }
    }
}

// ---------------- SIMT GEMM for tiny N=22 ------------------------------------
__global__ __launch_bounds__(256, 2)
void gemm_tn(const float* __restrict__ A, int lda,
             const float* __restrict__ B, int ldb,
             const float* __restrict__ bias,
             float* __restrict__ C, int ldc,
             int M, int N, int K)
{
    __shared__ float As[16][132];
    __shared__ float Bs[16][132];
    const int tid = threadIdx.x;
    const int bm = blockIdx.y * 128;
    const int bn = blockIdx.x * 128;
    const int tm = (tid >> 4) << 3;
    const int tn = (tid & 15) << 3;
    const int lr = tid >> 2;
    const int lc = (tid & 3) << 2;

    float acc[8][8];
#pragma unroll
    for (int i = 0; i < 8; i++)
#pragma unroll
        for (int j = 0; j < 8; j++) acc[i][j] = 0.0f;

    for (int k0 = 0; k0 < K; k0 += 16) {
#pragma unroll
        for (int h2 = 0; h2 < 2; h2++) {
            int r = lr + h2 * 64;
            const float4 v = *reinterpret_cast<const float4*>(&A[(size_t)(bm + r) * lda + k0 + lc]);
            As[lc + 0][r] = v.x; As[lc + 1][r] = v.y;
            As[lc + 2][r] = v.z; As[lc + 3][r] = v.w;
        }
#pragma unroll
        for (int h2 = 0; h2 < 2; h2++) {
            int r = lr + h2 * 64;
            float4 v = make_float4(0.f, 0.f, 0.f, 0.f);
            if (bn + r < N)
                v = *reinterpret_cast<const float4*>(&B[(size_t)(bn + r) * ldb + k0 + lc]);
            Bs[lc + 0][r] = v.x; Bs[lc + 1][r] = v.y;
            Bs[lc + 2][r] = v.z; Bs[lc + 3][r] = v.w;
        }
        __syncthreads();
#pragma unroll
        for (int k = 0; k < 16; k++) {
            float a[8], b[8];
            *reinterpret_cast<float4*>(&a[0]) = *reinterpret_cast<const float4*>(&As[k][tm]);
            *reinterpret_cast<float4*>(&a[4]) = *reinterpret_cast<const float4*>(&As[k][tm + 4]);
            *reinterpret_cast<float4*>(&b[0]) = *reinterpret_cast<const float4*>(&Bs[k][tn]);
            *reinterpret_cast<float4*>(&b[4]) = *reinterpret_cast<const float4*>(&Bs[k][tn + 4]);
#pragma unroll
            for (int i = 0; i < 8; i++)
#pragma unroll
                for (int j = 0; j < 8; j++)
                    acc[i][j] += a[i] * b[j];
        }
        __syncthreads();
    }
#pragma unroll
    for (int i = 0; i < 8; i++) {
        const int row = bm + tm + i;
        float* crow = C + (size_t)row * ldc;
#pragma unroll
        for (int j = 0; j < 8; j++) {
            const int col = bn + tn + j;
            if (col < N) {
                float v = acc[i][j];
                if (bias) v += bias[col];
                crow[col] = v;
            }
        }
    }
}

// ---------------- conversion / setup kernels ---------------------------------
__global__ void bias_perm(const float* __restrict__ a, const float* __restrict__ b,
                          float* __restrict__ out, int H)
{
    int i = blockIdx.x * blockDim.x + threadIdx.x;
    if (i >= 4 * H) return;
    int gate = i / H, unit = i - gate * H;
    out[unit * 4 + gate] = a[i] + b[i];
}

__global__ void cvt_w(const float* __restrict__ src, __half* __restrict__ dst, int n)
{
    int i = (blockIdx.x * blockDim.x + threadIdx.x) * 8;
    if (i >= n) return;
    float4 v0 = *reinterpret_cast<const float4*>(src + i);
    float4 v1 = *reinterpret_cast<const float4*>(src + i + 4);
    __half2 p0; p0.x = __float2half_rn(v0.x); p0.y = __float2half_rn(v0.y);
    __half2 p1; p1.x = __float2half_rn(v0.z); p1.y = __float2half_rn(v0.w);
    __half2 p2; p2.x = __float2half_rn(v1.x); p2.y = __float2half_rn(v1.y);
    __half2 p3; p3.x = __float2half_rn(v1.z); p3.y = __float2half_rn(v1.w);
    *reinterpret_cast<__half2*>(dst + i) = p0;
    *reinterpret_cast<__half2*>(dst + i + 2) = p1;
    *reinterpret_cast<__half2*>(dst + i + 4) = p2;
    *reinterpret_cast<__half2*>(dst + i + 6) = p3;
}

__global__ void cvt_w_perm(const float* __restrict__ src, __half* __restrict__ dst,
                           int H, int K, int n)
{
    int i = (blockIdx.x * blockDim.x + threadIdx.x) * 4;
    if (i >= n) return;
    int r = i / K, k = i - r * K;
    int gate = r / H, unit = r - gate * H;
    int o = (unit * 4 + gate) * K + k;
    float4 v = *reinterpret_cast<const float4*>(src + i);
    __half2 p0; p0.x = __float2half_rn(v.x); p0.y = __float2half_rn(v.y);
    __half2 p1; p1.x = __float2half_rn(v.z); p1.y = __float2half_rn(v.w);
    *reinterpret_cast<__half2*>(dst + o) = p0;
    *reinterpret_cast<__half2*>(dst + o + 2) = p1;
}

__global__ void cvt_w_T(const float* __restrict__ src, __half* __restrict__ dst,
                        int F, int H)
{
    int o = blockIdx.x * blockDim.x + threadIdx.x;
    if (o >= F * H) return;
    int j = o / F, k = o - j * F;
    dst[o] = __float2half_rn(src[(size_t)k * H + j]);
}

__global__ void cvt_add(const float* __restrict__ P, const float* __restrict__ Whh,
                        __half* __restrict__ dst, int H)
{
    int o = blockIdx.x * blockDim.x + threadIdx.x;
    if (o >= 4 * H * H) return;
    int r = o / H, j = o - r * H;
    int unit = r >> 2, gate = r & 3;
    dst[o] = __float2half_rn(P[o] + Whh[(size_t)(gate * H + unit) * H + j]);
}

__global__ void cvt_scale(const float* __restrict__ src, __half* __restrict__ dst,
                          float scale, int n)
{
    int i = blockIdx.x * blockDim.x + threadIdx.x;
    if (i < n) dst[i] = __float2half_rn(src[i] * scale);
}

__global__ void bias_comb(const float* __restrict__ base, const float* __restrict__ W,
                          const float* __restrict__ v, float* __restrict__ out,
                          int H, int K, float scale)
{
    int w = (blockIdx.x * blockDim.x + threadIdx.x) >> 5;
    int lane = threadIdx.x & 31;
    if (w >= 4 * H) return;
    int unit = w >> 2, gate = w & 3;
    const float* row = W + (size_t)(gate * H + unit) * K;
    float s = 0.0f;
    for (int k = lane; k < K; k += 32) s += row[k] * v[k];
#pragma unroll
    for (int off = 16; off; off >>= 1) s += __shfl_xor_sync(0xffffffffu, s, off);
    if (lane == 0) out[w] = base[w] + s * scale;
}

// ---------------- launch -----------------------------------------------------
extern "C" void kernel_launch(void* const* d_in, const int* in_sizes, int n_in,
                              void* d_out, int out_size)
{
    const float* x    = (const float*)d_in[0];
    const float* Wf   = (const float*)d_in[1];
    const float* bf_  = (const float*)d_in[2];
    const float* dWih = (const float*)d_in[3];
    const float* dWhh = (const float*)d_in[4];
    const float* dbih = (const float*)d_in[5];
    const float* dbhh = (const float*)d_in[6];
    const float* Wdc  = (const float*)d_in[7];
    const float* bdc  = (const float*)d_in[8];
    const float* eWih = (const float*)d_in[9];
    const float* eWhh = (const float*)d_in[10];
    const float* ebih = (const float*)d_in[11];
    const float* ebhh = (const float*)d_in[12];
    const float* Wec  = (const float*)d_in[13];
    const float* bec  = (const float*)d_in[14];

    float* out = (float*)d_out;
    float* dec = out + 64 * 64 * CDIM;

    float *h, *c, *bsd, *bse, *bcomb, *benc2;
    __half *x16, *Wf16, *dWih16, *Wdc16, *WdcT16, *Wc16, *eWih16, *eWhh16, *Wenc16;
    __half *f16, *hall;
    cudaGetSymbolAddress((void**)&h, g_h);
    cudaGetSymbolAddress((void**)&c, g_c);
    cudaGetSymbolAddress((void**)&bsd, g_bsum_dec);
    cudaGetSymbolAddress((void**)&bse, g_bsum_enc);
    cudaGetSymbolAddress((void**)&bcomb, g_bcomb);
    cudaGetSymbolAddress((void**)&benc2, g_benc2);
    cudaGetSymbolAddress((void**)&x16, g_x16);
    cudaGetSymbolAddress((void**)&Wf16, g_Wf16);
    cudaGetSymbolAddress((void**)&dWih16, g_dWih16);
    cudaGetSymbolAddress((void**)&Wdc16, g_Wdc16);
    cudaGetSymbolAddress((void**)&WdcT16, g_WdcT16);
    cudaGetSymbolAddress((void**)&Wc16, g_Wc16);
    cudaGetSymbolAddress((void**)&eWih16, g_eWih16);
    cudaGetSymbolAddress((void**)&eWhh16, g_eWhh16);
    cudaGetSymbolAddress((void**)&Wenc16, g_Wenc16);
    cudaGetSymbolAddress((void**)&f16, g_f16);
    cudaGetSymbolAddress((void**)&hall, g_hall);

    cudaFuncSetAttribute(tgemm, cudaFuncAttributeMaxDynamicSharedMemorySize, TG_SMEM);

    const dim3 blk(256);
    const size_t NH = (size_t)NROWS * HDIM;

    // ---- conversions ----
    cvt_w<<<NROWS * INDIM / 8 / 256, blk>>>(x, x16, NROWS * INDIM);
    cvt_w<<<FDIM * INDIM / 8 / 256, blk>>>(Wf, Wf16, FDIM * INDIM);
    cvt_w_perm<<<4 * HDIM * FDIM / 4 / 256, blk>>>(dWih, dWih16, HDIM, FDIM, 4 * HDIM * FDIM);
    cvt_w<<<FDIM * HDIM / 8 / 256, blk>>>(Wdc, Wdc16, FDIM * HDIM);
    cvt_w_T<<<(HDIM * FDIM + 255) / 256, blk>>>(Wdc, WdcT16, FDIM, HDIM);
    cvt_w_perm<<<4 * FDIM * FDIM / 4 / 256, blk>>>(eWih, eWih16, FDIM, FDIM, 4 * FDIM * FDIM);
    cvt_w_perm<<<4 * FDIM * FDIM / 4 / 256, blk>>>(eWhh, eWhh16, FDIM, FDIM, 4 * FDIM * FDIM);
    bias_perm<<<(4 * HDIM + 255) / 256, blk>>>(dbih, dbhh, bsd, HDIM);
    bias_perm<<<(4 * FDIM + 255) / 256, blk>>>(ebih, ebhh, bse, FDIM);
    bias_comb<<<4 * HDIM * 32 / 256, blk>>>(bsd, dWih, bdc, bcomb, HDIM, FDIM, 1.0f);
    bias_comb<<<4 * FDIM * 32 / 256, blk>>>(bse, eWhh, bdc, benc2, FDIM, FDIM, 1.0f / DSTEPS);

    // ---- precompute Wcomb = dWih@Wdc + dWhh -> fp16 (P in g_h) ----
    tgemm<<<dim3(HDIM / 256, 4 * HDIM / 128), blk, TG_SMEM>>>(
        dWih16, FDIM, WdcT16, FDIM, FDIM / 128,
        nullptr, 0, nullptr, 0, 0,
        nullptr, h, HDIM, nullptr, 0, 1.0f, 0,
        0, nullptr, nullptr, nullptr, nullptr, 0, 0);
    cvt_add<<<(4 * HDIM * HDIM + 255) / 256, blk>>>(h, dWhh, Wc16, HDIM);

    // ---- precompute Wenc = (eWhh@Wdc)/D -> fp16 (P2 in g_h) ----
    tgemm<<<dim3(HDIM / 256, 4 * FDIM / 128), blk, TG_SMEM>>>(
        eWhh16, FDIM, WdcT16, FDIM, FDIM / 128,
        nullptr, 0, nullptr, 0, 0,
        nullptr, h, HDIM, nullptr, 0, 1.0f, 0,
        0, nullptr, nullptr, nullptr, nullptr, 0, 0);
    cvt_scale<<<(4 * FDIM * HDIM + 255) / 256, blk>>>(h, Wenc16, 1.0f / DSTEPS, 4 * FDIM * HDIM);

    // ---- feats = relu(x @ Wf^T + bf) -> f16 ----
    tgemm<<<dim3(FDIM / 256, NROWS / 128), blk, TG_SMEM>>>(
        x16, INDIM, Wf16, INDIM, INDIM / 128,
        nullptr, 0, nullptr, 0, 0,
        bf_, nullptr, 0, f16, FDIM, 1.0f, 1,
        0, nullptr, nullptr, nullptr, nullptr, 0, 0);

    // ---- decoder recurrence: h_d -> hall[d] ----
    tgemm<<<dim3(4 * HDIM / 256, NROWS / 128), blk, TG_SMEM>>>(
        f16, FDIM, dWih16, FDIM, FDIM / 128,
        nullptr, 0, nullptr, 0, 0,
        bsd, nullptr, 0, nullptr, 0, 1.0f, 0,
        1, c, c, hall, nullptr, 1, 0);
    for (int d = 1; d < DSTEPS; d++) {
        tgemm<<<dim3(4 * HDIM / 256, NROWS / 128), blk, TG_SMEM>>>(
            hall + (size_t)(d - 1) * NH, HDIM, Wc16, HDIM, HDIM / 128,
            nullptr, 0, nullptr, 0, 0,
            bcomb, nullptr, 0, nullptr, 0, 1.0f, 0,
            1, c, c, hall + (size_t)d * NH, nullptr, 0, 0);
    }

    // ---- encoder ----
    tgemm<<<dim3(4 * FDIM / 256, NROWS / 128), blk, TG_SMEM>>>(
        f16, FDIM, eWih16, FDIM, FDIM / 128,
        hall + (size_t)(DSTEPS - 1) * NH, HDIM, Wenc16, HDIM, HDIM / 128,
        benc2, nullptr, 0, nullptr, 0, 1.0f, 0,
        2, nullptr, nullptr, nullptr, h, 1, 0);
    gemm_tn<<<dim3((CDIM + 127) / 128, NROWS / 128), blk>>>(
        h, FDIM, Wec, FDIM, bec, out, CDIM, NROWS, CDIM, FDIM);

    // ---- batched dec_scores: all 8 steps in one GEMM ----
    tgemm<<<dim3(FDIM / 256, DSTEPS * NROWS / 128), blk, TG_SMEM>>>(
        hall, HDIM, Wdc16, HDIM, HDIM / 128,
        nullptr, 0, nullptr, 0, 0,
        bdc, dec, 0, nullptr, 0, 1.0f, 0,
        0, nullptr, nullptr, nullptr, nullptr, 0, 1);
}

// round 13
// speedup vs baseline: 4.1306x; 1.0247x over previous
#include <cuda_runtime.h>
#include <cuda_fp16.h>
#include <stdint.h>
#include <math.h>

// B=64, T=64, D=8, F=1024, H=1024, C=22, IN=4096, N=B*T=4096
#define NROWS 4096
#define FDIM  1024
#define HDIM  1024
#define INDIM 4096
#define DSTEPS 8
#define CDIM  22

// ---------------- scratch (device globals) ----------------------------------
__device__ float g_h[4 * HDIM * HDIM];       // P/P2 scratch, then encoder h
__device__ float g_c[NROWS * HDIM];          // decoder cell state
__device__ float g_bsum_dec[4 * HDIM];
__device__ float g_bsum_enc[4 * FDIM];
__device__ float g_bcomb[4 * HDIM];          // bsd + dWih@bdc
__device__ float g_benc2[4 * FDIM];          // bse + eWhh@bdc/D

__device__ __align__(256) __half g_x16[NROWS * INDIM];
__device__ __align__(256) __half g_Wf16[FDIM * INDIM];
__device__ __align__(256) __half g_dWih16[4 * HDIM * FDIM];
__device__ __align__(256) __half g_Wdc16[FDIM * HDIM];
__device__ __align__(256) __half g_WdcT16[HDIM * FDIM];
__device__ __align__(256) __half g_Wc16[4 * HDIM * HDIM];
__device__ __align__(256) __half g_eWih16[4 * FDIM * FDIM];
__device__ __align__(256) __half g_eWhh16[4 * FDIM * FDIM];
__device__ __align__(256) __half g_Wenc16[4 * FDIM * HDIM];
__device__ __align__(256) __half g_f16[NROWS * FDIM];
__device__ __align__(256) __half g_hall[DSTEPS * NROWS * HDIM];

// ---------------- PTX helpers ------------------------------------------------
__device__ __forceinline__ uint32_t smem_u32(const void* p) {
    uint32_t a;
    asm("{ .reg .u64 t; cvta.to.shared.u64 t, %1; cvt.u32.u64 %0, t; }" : "=r"(a) : "l"(p));
    return a;
}
__device__ __forceinline__ void cpa16(uint32_t sa, const void* g) {
    asm volatile("cp.async.cg.shared.global [%0], [%1], 16;" :: "r"(sa), "l"(g));
}
__device__ __forceinline__ void cp_commit() {
    asm volatile("cp.async.commit_group;" ::: "memory");
}
template<int N> __device__ __forceinline__ void cp_wait() {
    asm volatile("cp.async.wait_group %0;" :: "n"(N) : "memory");
}
__device__ __forceinline__ void ldmx4(uint32_t* r, uint32_t addr) {
    asm volatile("ldmatrix.sync.aligned.m8n8.x4.shared.b16 {%0,%1,%2,%3}, [%4];"
                 : "=r"(r[0]), "=r"(r[1]), "=r"(r[2]), "=r"(r[3]) : "r"(addr));
}
__device__ __forceinline__ void mma16816(float* c, const uint32_t* a, const uint32_t* b) {
    asm volatile("mma.sync.aligned.m16n8k16.row.col.f32.f16.f16.f32 "
                 "{%0,%1,%2,%3}, {%4,%5,%6,%7}, {%8,%9}, {%0,%1,%2,%3};"
                 : "+f"(c[0]), "+f"(c[1]), "+f"(c[2]), "+f"(c[3])
                 : "r"(a[0]), "r"(a[1]), "r"(a[2]), "r"(a[3]), "r"(b[0]), "r"(b[1]));
}
__device__ __forceinline__ uint32_t swz(int row, int g) {
    return (uint32_t)(row * 128 + ((g ^ (row & 7)) << 4));
}
__device__ __forceinline__ float fsig(float x) {
    return __fdividef(1.0f, 1.0f + __expf(-x));
}
__device__ __forceinline__ float ftanh(float x) {
    float t = __expf(2.0f * x);
    return __fdividef(t - 1.0f, t + 1.0f);
}

// ---------------- tensor GEMM (templated on N-tile) ---------------------------
// NT=8: C tile 128x256 ; NT=4: C tile 128x128 (for wave-friendly square GEMMs).
// K-chunk = 128 per stage (two 64-wide sub-chunks), 2-stage cp.async pipeline.
#define SUB_A 16384

template<int NT>
__global__ __launch_bounds__(256, 1)
void tgemm(const __half* __restrict__ A1, int lda1,
           const __half* __restrict__ B1, int ldb1, int nk1,
           const __half* __restrict__ A2, int lda2,
           const __half* __restrict__ B2, int ldb2, int nk2,
           const float* __restrict__ bias, float* __restrict__ C, int ldc,
           __half* __restrict__ E, int lde, float escale, int relu,
           int cell, const float* __restrict__ cin, float* __restrict__ cout,
           __half* __restrict__ h16o, float* __restrict__ hfo, int czero,
           int decmode)
{
    constexpr int CN     = NT * 32;            // cols per CTA tile
    constexpr int SUB_B  = NT * 4096;          // B sub-chunk bytes (CN rows x 128B)
    constexpr int T_B    = 2 * SUB_A;
    constexpr int STAGE  = 2 * SUB_A + 2 * SUB_B;
    constexpr int SROWT  = CN + 4;             // fp32 staging row (floats)

    extern __shared__ __align__(1024) char sm[];
    const int tid = threadIdx.x;
    const int wid = tid >> 5;
    const int lane = tid & 31;
    const int wm = wid >> 2;
    const int wn = wid & 3;
    const int bm = blockIdx.y * 128;
    const int bn = blockIdx.x * CN;
    const uint32_t smb = smem_u32(sm);
    const int total = nk1 + nk2;

    float acc[4][NT][4];
#pragma unroll
    for (int i = 0; i < 4; i++)
#pragma unroll
        for (int j = 0; j < NT; j++)
#pragma unroll
            for (int k = 0; k < 4; k++) acc[i][j][k] = 0.0f;

    auto load_stage = [&](int q, int s) {
        const __half *a, *b; int la, lb, k0;
        if (q < nk1) { a = A1; b = B1; la = lda1; lb = ldb1; k0 = q * 128; }
        else         { a = A2; b = B2; la = lda2; lb = ldb2; k0 = (q - nk1) * 128; }
        const uint32_t sb = smb + (uint32_t)s * STAGE;
#pragma unroll
        for (int cch = 0; cch < 2; cch++) {
            const int kk = k0 + cch * 64;
#pragma unroll
            for (int i = 0; i < 4; i++) {
                int v = tid + i * 256;
                int row = v >> 3, g = v & 7;
                cpa16(sb + cch * SUB_A + swz(row, g),
                      a + (size_t)(bm + row) * la + kk + g * 8);
            }
#pragma unroll
            for (int i = 0; i < NT; i++) {
                int v = tid + i * 256;
                int row = v >> 3, g = v & 7;
                cpa16(sb + T_B + cch * SUB_B + swz(row, g),
                      b + (size_t)(bn + row) * lb + kk + g * 8);
            }
        }
        cp_commit();
    };

    const int r8 = lane & 7;
    const int arow0 = wm * 64 + r8 + 8 * ((lane >> 3) & 1);
    const int akq   = lane >> 4;
    const int brow0 = wn * (NT * 8) + r8 + 8 * (lane >> 4);
    const int bkq   = (lane >> 3) & 1;

    load_stage(0, 0);

    for (int q = 0; q < total; q++) {
        const int s = q & 1;
        if (q + 1 < total) { load_stage(q + 1, s ^ 1); cp_wait<1>(); }
        else               { cp_wait<0>(); }
        __syncthreads();

        const uint32_t sb = smb + (uint32_t)s * STAGE;
#pragma unroll
        for (int cch = 0; cch < 2; cch++) {
            const uint32_t ab = sb + cch * SUB_A;
            const uint32_t bb = sb + T_B + cch * SUB_B;
#pragma unroll
            for (int ks = 0; ks < 4; ks++) {
                uint32_t a[4][4];
#pragma unroll
                for (int mt = 0; mt < 4; mt++)
                    ldmx4(a[mt], ab + swz(arow0 + mt * 16, ks * 2 + akq));
                uint32_t b[NT][2];
#pragma unroll
                for (int p = 0; p < NT / 2; p++) {
                    uint32_t t[4];
                    ldmx4(t, bb + swz(brow0 + p * 16, ks * 2 + bkq));
                    b[2 * p][0] = t[0]; b[2 * p][1] = t[1];
                    b[2 * p + 1][0] = t[2]; b[2 * p + 1][1] = t[3];
                }
#pragma unroll
                for (int mt = 0; mt < 4; mt++)
#pragma unroll
                    for (int nt = 0; nt < NT; nt++)
                        mma16816(acc[mt][nt], a[mt], b[nt]);
            }
        }
        __syncthreads();
    }

    if (cell == 0) {
        // ---- plain epilogue (decmode scatters into [N, D, F]) ----
#pragma unroll
        for (int mt = 0; mt < 4; mt++) {
#pragma unroll
            for (int nt = 0; nt < NT; nt++) {
                const int row = bm + wm * 64 + mt * 16 + (lane >> 2);
                const int col = bn + wn * (NT * 8) + nt * 8 + (lane & 3) * 2;
#pragma unroll
                for (int hh2 = 0; hh2 < 2; hh2++) {
                    const int rr = row + hh2 * 8;
                    float v0 = acc[mt][nt][2 * hh2];
                    float v1 = acc[mt][nt][2 * hh2 + 1];
                    if (bias) { v0 += bias[col]; v1 += bias[col + 1]; }
                    if (relu) { v0 = fmaxf(v0, 0.0f); v1 = fmaxf(v1, 0.0f); }
                    if (C) {
                        float* crow;
                        if (decmode) {
                            int dd = rr >> 12, r2 = rr & 4095;
                            crow = C + (size_t)r2 * (DSTEPS * FDIM) + dd * FDIM;
                        } else {
                            crow = C + (size_t)rr * ldc;
                        }
                        *reinterpret_cast<float2*>(crow + col) = make_float2(v0, v1);
                    }
                    if (E) {
                        __half2 hp;
                        hp.x = __float2half_rn(v0 * escale);
                        hp.y = __float2half_rn(v1 * escale);
                        *reinterpret_cast<__half2*>(E + (size_t)rr * lde + col) = hp;
                    }
                }
            }
        }
    } else {
        // ---- fused LSTM cell via smem-staged gates ----
        float* sg = reinterpret_cast<float*>(sm);
#pragma unroll
        for (int mt = 0; mt < 4; mt++) {
#pragma unroll
            for (int nt = 0; nt < NT; nt++) {
                const int rL = wm * 64 + mt * 16 + (lane >> 2);
                const int cL = wn * (NT * 8) + nt * 8 + (lane & 3) * 2;
                const int cG = bn + cL;
#pragma unroll
                for (int hh2 = 0; hh2 < 2; hh2++) {
                    float v0 = acc[mt][nt][2 * hh2]     + bias[cG];
                    float v1 = acc[mt][nt][2 * hh2 + 1] + bias[cG + 1];
                    *reinterpret_cast<float2*>(&sg[(rL + hh2 * 8) * SROWT + cL]) =
                        make_float2(v0, v1);
                }
            }
        }
        __syncthreads();
        // unit-major pass: U units per tile, 256/U row-groups
        constexpr int U  = NT * 8;     // units per tile (CN/4)
        constexpr int NG = 256 / U;    // row groups
        const int u  = tid % U;
        const int rg = tid / U;
        const int jG = (bn >> 2) + u;
#pragma unroll 4
        for (int k = 0; k < 128 / NG; k++) {
            const int rL = NG * k + rg;
            float4 gv = *reinterpret_cast<const float4*>(&sg[rL * SROWT + u * 4]);
            const size_t oidx = (size_t)(bm + rL) * HDIM + jG;
            float cprev = czero ? 0.0f : cin[oidx];
            float cn = fsig(gv.y) * cprev + fsig(gv.x) * ftanh(gv.z);
            float hn = fsig(gv.w) * ftanh(cn);
            if (cout) cout[oidx] = cn;
            if (h16o) h16o[oidx] = __float2half_rn(hn);
            if (hfo)  hfo[oidx] = hn;
        }
    }
}

#define TG_SMEM8 (2 * (2 * SUB_A + 2 * 8 * 4096))   // 196608
#define TG_SMEM4 (2 * (2 * SUB_A + 2 * 4 * 4096))   // 131072

// ---------------- SIMT GEMM for tiny N=22 ------------------------------------
__global__ __launch_bounds__(256, 2)
void gemm_tn(const float* __restrict__ A, int lda,
             const float* __restrict__ B, int ldb,
             const float* __restrict__ bias,
             float* __restrict__ C, int ldc,
             int M, int N, int K)
{
    __shared__ float As[16][132];
    __shared__ float Bs[16][132];
    const int tid = threadIdx.x;
    const int bm = blockIdx.y * 128;
    const int bn = blockIdx.x * 128;
    const int tm = (tid >> 4) << 3;
    const int tn = (tid & 15) << 3;
    const int lr = tid >> 2;
    const int lc = (tid & 3) << 2;

    float acc[8][8];
#pragma unroll
    for (int i = 0; i < 8; i++)
#pragma unroll
        for (int j = 0; j < 8; j++) acc[i][j] = 0.0f;

    for (int k0 = 0; k0 < K; k0 += 16) {
#pragma unroll
        for (int h2 = 0; h2 < 2; h2++) {
            int r = lr + h2 * 64;
            const float4 v = *reinterpret_cast<const float4*>(&A[(size_t)(bm + r) * lda + k0 + lc]);
            As[lc + 0][r] = v.x; As[lc + 1][r] = v.y;
            As[lc + 2][r] = v.z; As[lc + 3][r] = v.w;
        }
#pragma unroll
        for (int h2 = 0; h2 < 2; h2++) {
            int r = lr + h2 * 64;
            float4 v = make_float4(0.f, 0.f, 0.f, 0.f);
            if (bn + r < N)
                v = *reinterpret_cast<const float4*>(&B[(size_t)(bn + r) * ldb + k0 + lc]);
            Bs[lc + 0][r] = v.x; Bs[lc + 1][r] = v.y;
            Bs[lc + 2][r] = v.z; Bs[lc + 3][r] = v.w;
        }
        __syncthreads();
#pragma unroll
        for (int k = 0; k < 16; k++) {
            float a[8], b[8];
            *reinterpret_cast<float4*>(&a[0]) = *reinterpret_cast<const float4*>(&As[k][tm]);
            *reinterpret_cast<float4*>(&a[4]) = *reinterpret_cast<const float4*>(&As[k][tm + 4]);
            *reinterpret_cast<float4*>(&b[0]) = *reinterpret_cast<const float4*>(&Bs[k][tn]);
            *reinterpret_cast<float4*>(&b[4]) = *reinterpret_cast<const float4*>(&Bs[k][tn + 4]);
#pragma unroll
            for (int i = 0; i < 8; i++)
#pragma unroll
                for (int j = 0; j < 8; j++)
                    acc[i][j] += a[i] * b[j];
        }
        __syncthreads();
    }
#pragma unroll
    for (int i = 0; i < 8; i++) {
        const int row = bm + tm + i;
        float* crow = C + (size_t)row * ldc;
#pragma unroll
        for (int j = 0; j < 8; j++) {
            const int col = bn + tn + j;
            if (col < N) {
                float v = acc[i][j];
                if (bias) v += bias[col];
                crow[col] = v;
            }
        }
    }
}

// ---------------- conversion / setup kernels ---------------------------------
__global__ void bias_perm(const float* __restrict__ a, const float* __restrict__ b,
                          float* __restrict__ out, int H)
{
    int i = blockIdx.x * blockDim.x + threadIdx.x;
    if (i >= 4 * H) return;
    int gate = i / H, unit = i - gate * H;
    out[unit * 4 + gate] = a[i] + b[i];
}

__global__ void cvt_w(const float* __restrict__ src, __half* __restrict__ dst, int n)
{
    int i = (blockIdx.x * blockDim.x + threadIdx.x) * 8;
    if (i >= n) return;
    float4 v0 = *reinterpret_cast<const float4*>(src + i);
    float4 v1 = *reinterpret_cast<const float4*>(src + i + 4);
    __half2 p0; p0.x = __float2half_rn(v0.x); p0.y = __float2half_rn(v0.y);
    __half2 p1; p1.x = __float2half_rn(v0.z); p1.y = __float2half_rn(v0.w);
    __half2 p2; p2.x = __float2half_rn(v1.x); p2.y = __float2half_rn(v1.y);
    __half2 p3; p3.x = __float2half_rn(v1.z); p3.y = __float2half_rn(v1.w);
    *reinterpret_cast<__half2*>(dst + i) = p0;
    *reinterpret_cast<__half2*>(dst + i + 2) = p1;
    *reinterpret_cast<__half2*>(dst + i + 4) = p2;
    *reinterpret_cast<__half2*>(dst + i + 6) = p3;
}

__global__ void cvt_w_perm(const float* __restrict__ src, __half* __restrict__ dst,
                           int H, int K, int n)
{
    int i = (blockIdx.x * blockDim.x + threadIdx.x) * 4;
    if (i >= n) return;
    int r = i / K, k = i - r * K;
    int gate = r / H, unit = r - gate * H;
    int o = (unit * 4 + gate) * K + k;
    float4 v = *reinterpret_cast<const float4*>(src + i);
    __half2 p0; p0.x = __float2half_rn(v.x); p0.y = __float2half_rn(v.y);
    __half2 p1; p1.x = __float2half_rn(v.z); p1.y = __float2half_rn(v.w);
    *reinterpret_cast<__half2*>(dst + o) = p0;
    *reinterpret_cast<__half2*>(dst + o + 2) = p1;
}

__global__ void cvt_w_T(const float* __restrict__ src, __half* __restrict__ dst,
                        int F, int H)
{
    int o = blockIdx.x * blockDim.x + threadIdx.x;
    if (o >= F * H) return;
    int j = o / F, k = o - j * F;
    dst[o] = __float2half_rn(src[(size_t)k * H + j]);
}

__global__ void cvt_add(const float* __restrict__ P, const float* __restrict__ Whh,
                        __half* __restrict__ dst, int H)
{
    int o = blockIdx.x * blockDim.x + threadIdx.x;
    if (o >= 4 * H * H) return;
    int r = o / H, j = o - r * H;
    int unit = r >> 2, gate = r & 3;
    dst[o] = __float2half_rn(P[o] + Whh[(size_t)(gate * H + unit) * H + j]);
}

__global__ void cvt_scale(const float* __restrict__ src, __half* __restrict__ dst,
                          float scale, int n)
{
    int i = blockIdx.x * blockDim.x + threadIdx.x;
    if (i < n) dst[i] = __float2half_rn(src[i] * scale);
}

__global__ void bias_comb(const float* __restrict__ base, const float* __restrict__ W,
                          const float* __restrict__ v, float* __restrict__ out,
                          int H, int K, float scale)
{
    int w = (blockIdx.x * blockDim.x + threadIdx.x) >> 5;
    int lane = threadIdx.x & 31;
    if (w >= 4 * H) return;
    int unit = w >> 2, gate = w & 3;
    const float* row = W + (size_t)(gate * H + unit) * K;
    float s = 0.0f;
    for (int k = lane; k < K; k += 32) s += row[k] * v[k];
#pragma unroll
    for (int off = 16; off; off >>= 1) s += __shfl_xor_sync(0xffffffffu, s, off);
    if (lane == 0) out[w] = base[w] + s * scale;
}

// ---------------- launch -----------------------------------------------------
extern "C" void kernel_launch(void* const* d_in, const int* in_sizes, int n_in,
                              void* d_out, int out_size)
{
    const float* x    = (const float*)d_in[0];
    const float* Wf   = (const float*)d_in[1];
    const float* bf_  = (const float*)d_in[2];
    const float* dWih = (const float*)d_in[3];
    const float* dWhh = (const float*)d_in[4];
    const float* dbih = (const float*)d_in[5];
    const float* dbhh = (const float*)d_in[6];
    const float* Wdc  = (const float*)d_in[7];
    const float* bdc  = (const float*)d_in[8];
    const float* eWih = (const float*)d_in[9];
    const float* eWhh = (const float*)d_in[10];
    const float* ebih = (const float*)d_in[11];
    const float* ebhh = (const float*)d_in[12];
    const float* Wec  = (const float*)d_in[13];
    const float* bec  = (const float*)d_in[14];

    float* out = (float*)d_out;
    float* dec = out + 64 * 64 * CDIM;

    float *h, *c, *bsd, *bse, *bcomb, *benc2;
    __half *x16, *Wf16, *dWih16, *Wdc16, *WdcT16, *Wc16, *eWih16, *eWhh16, *Wenc16;
    __half *f16, *hall;
    cudaGetSymbolAddress((void**)&h, g_h);
    cudaGetSymbolAddress((void**)&c, g_c);
    cudaGetSymbolAddress((void**)&bsd, g_bsum_dec);
    cudaGetSymbolAddress((void**)&bse, g_bsum_enc);
    cudaGetSymbolAddress((void**)&bcomb, g_bcomb);
    cudaGetSymbolAddress((void**)&benc2, g_benc2);
    cudaGetSymbolAddress((void**)&x16, g_x16);
    cudaGetSymbolAddress((void**)&Wf16, g_Wf16);
    cudaGetSymbolAddress((void**)&dWih16, g_dWih16);
    cudaGetSymbolAddress((void**)&Wdc16, g_Wdc16);
    cudaGetSymbolAddress((void**)&WdcT16, g_WdcT16);
    cudaGetSymbolAddress((void**)&Wc16, g_Wc16);
    cudaGetSymbolAddress((void**)&eWih16, g_eWih16);
    cudaGetSymbolAddress((void**)&eWhh16, g_eWhh16);
    cudaGetSymbolAddress((void**)&Wenc16, g_Wenc16);
    cudaGetSymbolAddress((void**)&f16, g_f16);
    cudaGetSymbolAddress((void**)&hall, g_hall);

    cudaFuncSetAttribute(tgemm<8>, cudaFuncAttributeMaxDynamicSharedMemorySize, TG_SMEM8);
    cudaFuncSetAttribute(tgemm<4>, cudaFuncAttributeMaxDynamicSharedMemorySize, TG_SMEM4);

    const dim3 blk(256);
    const size_t NH = (size_t)NROWS * HDIM;

    // ---- conversions ----
    cvt_w<<<NROWS * INDIM / 8 / 256, blk>>>(x, x16, NROWS * INDIM);
    cvt_w<<<FDIM * INDIM / 8 / 256, blk>>>(Wf, Wf16, FDIM * INDIM);
    cvt_w_perm<<<4 * HDIM * FDIM / 4 / 256, blk>>>(dWih, dWih16, HDIM, FDIM, 4 * HDIM * FDIM);
    cvt_w<<<FDIM * HDIM / 8 / 256, blk>>>(Wdc, Wdc16, FDIM * HDIM);
    cvt_w_T<<<(HDIM * FDIM + 255) / 256, blk>>>(Wdc, WdcT16, FDIM, HDIM);
    cvt_w_perm<<<4 * FDIM * FDIM / 4 / 256, blk>>>(eWih, eWih16, FDIM, FDIM, 4 * FDIM * FDIM);
    cvt_w_perm<<<4 * FDIM * FDIM / 4 / 256, blk>>>(eWhh, eWhh16, FDIM, FDIM, 4 * FDIM * FDIM);
    bias_perm<<<(4 * HDIM + 255) / 256, blk>>>(dbih, dbhh, bsd, HDIM);
    bias_perm<<<(4 * FDIM + 255) / 256, blk>>>(ebih, ebhh, bse, FDIM);
    bias_comb<<<4 * HDIM * 32 / 256, blk>>>(bsd, dWih, bdc, bcomb, HDIM, FDIM, 1.0f);
    bias_comb<<<4 * FDIM * 32 / 256, blk>>>(bse, eWhh, bdc, benc2, FDIM, FDIM, 1.0f / DSTEPS);

    // ---- precompute Wcomb = dWih@Wdc + dWhh -> fp16 (P in g_h) ----
    tgemm<8><<<dim3(HDIM / 256, 4 * HDIM / 128), blk, TG_SMEM8>>>(
        dWih16, FDIM, WdcT16, FDIM, FDIM / 128,
        nullptr, 0, nullptr, 0, 0,
        nullptr, h, HDIM, nullptr, 0, 1.0f, 0,
        0, nullptr, nullptr, nullptr, nullptr, 0, 0);
    cvt_add<<<(4 * HDIM * HDIM + 255) / 256, blk>>>(h, dWhh, Wc16, HDIM);

    // ---- precompute Wenc = (eWhh@Wdc)/D -> fp16 (P2 in g_h) ----
    tgemm<8><<<dim3(HDIM / 256, 4 * FDIM / 128), blk, TG_SMEM8>>>(
        eWhh16, FDIM, WdcT16, FDIM, FDIM / 128,
        nullptr, 0, nullptr, 0, 0,
        nullptr, h, HDIM, nullptr, 0, 1.0f, 0,
        0, nullptr, nullptr, nullptr, nullptr, 0, 0);
    cvt_scale<<<(4 * FDIM * HDIM + 255) / 256, blk>>>(h, Wenc16, 1.0f / DSTEPS, 4 * FDIM * HDIM);

    // ---- feats = relu(x @ Wf^T + bf) -> f16 ----
    tgemm<8><<<dim3(FDIM / 256, NROWS / 128), blk, TG_SMEM8>>>(
        x16, INDIM, Wf16, INDIM, INDIM / 128,
        nullptr, 0, nullptr, 0, 0,
        bf_, nullptr, 0, f16, FDIM, 1.0f, 1,
        0, nullptr, nullptr, nullptr, nullptr, 0, 0);

    // ---- decoder recurrence: NT=4 tiles (1024 CTAs, ~1% wave waste) ----
    tgemm<4><<<dim3(4 * HDIM / 128, NROWS / 128), blk, TG_SMEM4>>>(
        f16, FDIM, dWih16, FDIM, FDIM / 128,
        nullptr, 0, nullptr, 0, 0,
        bsd, nullptr, 0, nullptr, 0, 1.0f, 0,
        1, c, c, hall, nullptr, 1, 0);
    for (int d = 1; d < DSTEPS; d++) {
        tgemm<4><<<dim3(4 * HDIM / 128, NROWS / 128), blk, TG_SMEM4>>>(
            hall + (size_t)(d - 1) * NH, HDIM, Wc16, HDIM, HDIM / 128,
            nullptr, 0, nullptr, 0, 0,
            bcomb, nullptr, 0, nullptr, 0, 1.0f, 0,
            1, c, c, hall + (size_t)d * NH, nullptr, 0, 0);
    }

    // ---- encoder (NT=4) ----
    tgemm<4><<<dim3(4 * FDIM / 128, NROWS / 128), blk, TG_SMEM4>>>(
        f16, FDIM, eWih16, FDIM, FDIM / 128,
        hall + (size_t)(DSTEPS - 1) * NH, HDIM, Wenc16, HDIM, HDIM / 128,
        benc2, nullptr, 0, nullptr, 0, 1.0f, 0,
        2, nullptr, nullptr, nullptr, h, 1, 0);
    gemm_tn<<<dim3((CDIM + 127) / 128, NROWS / 128), blk>>>(
        h, FDIM, Wec, FDIM, bec, out, CDIM, NROWS, CDIM, FDIM);

    // ---- batched dec_scores: all 8 steps in one GEMM (NT=8, 1024 CTAs) ----
    tgemm<8><<<dim3(FDIM / 256, DSTEPS * NROWS / 128), blk, TG_SMEM8>>>(
        hall, HDIM, Wdc16, HDIM, HDIM / 128,
        nullptr, 0, nullptr, 0, 0,
        bdc, dec, 0, nullptr, 0, 1.0f, 0,
        0, nullptr, nullptr, nullptr, nullptr, 0, 1);
}